// round 1
// baseline (speedup 1.0000x reference)
#include <cuda_runtime.h>
#include <float.h>

// Problem constants
#define Bn   8
#define Hn   64
#define Wn   64
#define Cn   384
#define NHd  8
#define Dh   48
#define Rr   4
#define TK   4
#define HCn  16
#define WCn  16
#define NCn  256          // HCn*WCn
#define HWn  4096         // Hn*Wn
#define C3n  1152         // 3*Cn
#define SCALE 0.14433756729740643f  // 1/sqrt(48)

// ---------------- scratch (device globals; no allocation) ----------------
__device__ float g_xc  [Bn * NCn * Cn];        // pooled coarse tokens (B,Nc,C)
__device__ float g_qkvc[Bn * NCn * C3n];       // coarse QKV
__device__ int   g_topk[Bn * NHd * NCn * TK];  // routing indices
__device__ float g_xo  [Bn * NCn * Cn];        // coarse attn out (B,Hc,Wc,C)
__device__ float g_qkvf[Bn * HWn * C3n];       // fine QKV (151MB)
__device__ float g_yo  [Bn * HWn * Cn];        // fine attn out (B,H,W,C)
__device__ float g_z   [Bn * HWn * Cn];        // mixed
__device__ float g_z2  [Bn * HWn * Cn];        // after 2nd dwconv

// ---------------- K1: 4x4 average pool ----------------
__global__ __launch_bounds__(384) void pool_kernel(const float* __restrict__ x)
{
    int blk = blockIdx.x;          // b*256 + n
    int n = blk & 255, b = blk >> 8;
    int hc = n >> 4, wc = n & 15;
    int c = threadIdx.x;
    float s = 0.f;
#pragma unroll
    for (int i = 0; i < 4; i++)
#pragma unroll
        for (int j = 0; j < 4; j++)
            s += x[(((size_t)(b * Hn + hc * 4 + i)) * Wn + wc * 4 + j) * Cn + c];
    g_xc[((size_t)(b * NCn + n)) * Cn + c] = s * 0.0625f;
}

// ---------------- generic SGEMM:  O[M,N] = A[M,K] * W[N,K]^T (+bias) -------
// mode 0: A=g_xc,  O=g_qkvc   (coarse QKV)
// mode 1: A=Aext,  O=g_qkvf   (fine QKV, A = x)
// mode 2: A=g_z2,  O=Oext     (pointwise, bias)
__global__ __launch_bounds__(256) void gemm_tn(
    const float* __restrict__ Aext, const float* __restrict__ Wm,
    const float* __restrict__ bias, float* __restrict__ Oext,
    int M, int N, int K, int mode)
{
    const float* A = (mode == 0) ? g_xc : (mode == 2) ? g_z2 : Aext;
    float*       O = (mode == 0) ? g_qkvc : (mode == 1) ? g_qkvf : Oext;

    __shared__ float As[16][68];
    __shared__ float Bs[16][68];

    int tid = threadIdx.x;
    int tx = tid & 15, ty = tid >> 4;
    int lr = tid >> 2, lc = (tid & 3) << 2;

    const float* Ab = A  + ((size_t)(blockIdx.y * 64 + lr)) * K + lc;
    const float* Wb = Wm + ((size_t)(blockIdx.x * 64 + lr)) * K + lc;

    float acc[4][4];
#pragma unroll
    for (int i = 0; i < 4; i++)
#pragma unroll
        for (int j = 0; j < 4; j++) acc[i][j] = 0.f;

    for (int k0 = 0; k0 < K; k0 += 16) {
        float4 a  = *(const float4*)(Ab + k0);
        float4 bb = *(const float4*)(Wb + k0);
        As[lc + 0][lr] = a.x;  As[lc + 1][lr] = a.y;
        As[lc + 2][lr] = a.z;  As[lc + 3][lr] = a.w;
        Bs[lc + 0][lr] = bb.x; Bs[lc + 1][lr] = bb.y;
        Bs[lc + 2][lr] = bb.z; Bs[lc + 3][lr] = bb.w;
        __syncthreads();
#pragma unroll
        for (int kk = 0; kk < 16; kk++) {
            float4 av = *(const float4*)&As[kk][ty << 2];
            float4 bv = *(const float4*)&Bs[kk][tx << 2];
            float a4[4] = {av.x, av.y, av.z, av.w};
            float b4[4] = {bv.x, bv.y, bv.z, bv.w};
#pragma unroll
            for (int i = 0; i < 4; i++)
#pragma unroll
                for (int j = 0; j < 4; j++) acc[i][j] += a4[i] * b4[j];
        }
        __syncthreads();
    }

    int col0 = blockIdx.x * 64 + (tx << 2);
    float b4[4] = {0.f, 0.f, 0.f, 0.f};
    if (bias) {
#pragma unroll
        for (int j = 0; j < 4; j++) b4[j] = bias[col0 + j];
    }
#pragma unroll
    for (int i = 0; i < 4; i++) {
        int row = blockIdx.y * 64 + (ty << 2) + i;
        float4 r;
        r.x = acc[i][0] + b4[0]; r.y = acc[i][1] + b4[1];
        r.z = acc[i][2] + b4[2]; r.w = acc[i][3] + b4[3];
        *(float4*)&O[(size_t)row * N + col0] = r;
    }
}

// ---------------- K3: coarse routing attention + top-k ----------------
// one block per (b, h, q): 256 threads, each owns one key
__global__ __launch_bounds__(256) void coarse_attn_kernel()
{
    int bid = blockIdx.x;                 // b*2048 + hd*256 + q
    int q  = bid & 255;
    int hd = (bid >> 8) & 7;
    int b  = bid >> 11;

    __shared__ float logits[256];
    __shared__ float red[256];
    __shared__ int   redi[256];
    __shared__ float qv[Dh];
    __shared__ float part[4][Dh];
    __shared__ float s_max, s_inv;

    int tid = threadIdx.x;
    const float* base = g_qkvc + (size_t)b * NCn * C3n;

    if (tid < Dh) qv[tid] = base[(size_t)q * C3n + hd * Dh + tid];
    __syncthreads();

    // logit for key tid
    const float* krow = base + (size_t)tid * C3n + Cn + hd * Dh;
    float s = 0.f;
#pragma unroll
    for (int dd = 0; dd < Dh; dd++) s += qv[dd] * krow[dd];
    s *= SCALE;
    logits[tid] = s;

    // top-4 by iterative argmax
    float work = s;
    for (int t = 0; t < 4; t++) {
        red[tid] = work; redi[tid] = tid;
        __syncthreads();
        for (int off = 128; off > 0; off >>= 1) {
            if (tid < off) {
                float ov = red[tid + off];
                int   oi = redi[tid + off];
                if (ov > red[tid] || (ov == red[tid] && oi < redi[tid])) {
                    red[tid] = ov; redi[tid] = oi;
                }
            }
            __syncthreads();
        }
        if (tid == 0) {
            g_topk[(size_t)bid * 4 + t] = redi[0];
            if (t == 0) s_max = red[0];
        }
        __syncthreads();
        if (tid == redi[0]) work = -FLT_MAX;
        __syncthreads();
    }

    // softmax over all 256 keys
    float p = __expf(logits[tid] - s_max);
    red[tid] = p;
    __syncthreads();
    for (int off = 128; off > 0; off >>= 1) {
        if (tid < off) red[tid] += red[tid + off];
        __syncthreads();
    }
    if (tid == 0) s_inv = 1.f / red[0];
    __syncthreads();
    logits[tid] = p * s_inv;     // attention weights
    __syncthreads();

    // xo[q, hd*48+dd] = sum_j w_j * V[j,dd]   (192 threads: 4 key-groups x 48 dims)
    int g = tid / Dh, dd = tid % Dh;
    if (g < 4) {
        const float* vb = base + Cn * 2 + hd * Dh + dd;
        float acc = 0.f;
        int j0 = g * 64;
#pragma unroll 4
        for (int j = j0; j < j0 + 64; j++)
            acc += logits[j] * vb[(size_t)j * C3n];
        part[g][dd] = acc;
    }
    __syncthreads();
    if (tid < Dh) {
        float r = part[0][tid] + part[1][tid] + part[2][tid] + part[3][tid];
        g_xo[((size_t)(b * NCn + q)) * Cn + hd * Dh + tid] = r;
    }
}

// ---------------- K5: fine windowed attention over gathered windows -------
// one block per (b, h, n): 128 threads
__global__ __launch_bounds__(128) void fine_attn_kernel()
{
    int bid = blockIdx.x;                 // b*2048 + hd*256 + n
    int n  = bid & 255;
    int hd = (bid >> 8) & 7;
    int b  = bid >> 11;

    __shared__ float Qs[16][49];
    __shared__ float Ks[64][49];
    __shared__ float Vs[64][49];
    __shared__ float A2[16][64];
    __shared__ int   wins[4];

    int tid = threadIdx.x;
    int hc = n >> 4, wc = n & 15;
    const float* base = g_qkvf + (size_t)b * HWn * C3n;

    if (tid < 4) wins[tid] = g_topk[(size_t)bid * 4 + tid];

    for (int idx = tid; idx < 16 * Dh; idx += 128) {
        int p = idx / Dh, dd = idx % Dh;
        int s = (hc * 4 + (p >> 2)) * Wn + wc * 4 + (p & 3);
        Qs[p][dd] = base[(size_t)s * C3n + hd * Dh + dd];
    }
    __syncthreads();

    for (int idx = tid; idx < 64 * Dh; idx += 128) {
        int p = idx / Dh, dd = idx % Dh;
        int t = p >> 4, pl = p & 15;
        int m = wins[t];
        int s = ((m >> 4) * 4 + (pl >> 2)) * Wn + (m & 15) * 4 + (pl & 3);
        const float* row = base + (size_t)s * C3n + hd * Dh + dd;
        Ks[p][dd] = row[Cn];
        Vs[p][dd] = row[2 * Cn];
    }
    __syncthreads();

    // a2 = Qw Kg^T * scale   (16x64)
    for (int idx = tid; idx < 16 * 64; idx += 128) {
        int qq = idx >> 6, kk = idx & 63;
        float s = 0.f;
#pragma unroll
        for (int dd = 0; dd < Dh; dd++) s += Qs[qq][dd] * Ks[kk][dd];
        A2[qq][kk] = s * SCALE;
    }
    __syncthreads();

    // row softmax (16 rows, one thread each)
    if (tid < 16) {
        float m = -FLT_MAX;
#pragma unroll
        for (int kk = 0; kk < 64; kk++) m = fmaxf(m, A2[tid][kk]);
        float sum = 0.f;
#pragma unroll
        for (int kk = 0; kk < 64; kk++) {
            float e = __expf(A2[tid][kk] - m);
            A2[tid][kk] = e; sum += e;
        }
        float inv = 1.f / sum;
#pragma unroll
        for (int kk = 0; kk < 64; kk++) A2[tid][kk] *= inv;
    }
    __syncthreads();

    // yo = a2 @ Vg  -> scatter to (B,H,W,C)
    for (int idx = tid; idx < 16 * Dh; idx += 128) {
        int p = idx / Dh, dd = idx % Dh;
        float acc = 0.f;
#pragma unroll
        for (int kk = 0; kk < 64; kk++) acc += A2[p][kk] * Vs[kk][dd];
        int yy = hc * 4 + (p >> 2), xx = wc * 4 + (p & 3);
        g_yo[(((size_t)(b * Hn + yy)) * Wn + xx) * Cn + hd * Dh + dd] = acc;
    }
}

// ---------------- K6: upsample(xo) -> dwconv3x3(dwx) -> mix with yo -------
// grid: B*H (one image row per block), 384 threads (one channel each)
__global__ __launch_bounds__(384) void dwmix_kernel(
    const float* __restrict__ dwxw, const float* __restrict__ dwxb)
{
    __shared__ float wsh[Cn * 9];
    __shared__ float bsh[Cn];
    int tid = threadIdx.x;
    for (int i = tid; i < Cn * 9; i += 384) wsh[i] = dwxw[i];
    bsh[tid] = dwxb[tid];
    __syncthreads();

    int b  = blockIdx.x >> 6;
    int yy = blockIdx.x & 63;
    int c  = tid;
    const float* wc9 = &wsh[c * 9];
    float w[9];
#pragma unroll
    for (int i = 0; i < 9; i++) w[i] = wc9[i];

    for (int xx = 0; xx < Wn; xx++) {
        float acc = bsh[c];
#pragma unroll
        for (int di = -1; di <= 1; di++) {
            int y2 = yy + di;
            if (y2 < 0 || y2 >= Hn) continue;
#pragma unroll
            for (int dj = -1; dj <= 1; dj++) {
                int x2 = xx + dj;
                if (x2 < 0 || x2 >= Wn) continue;
                float v = g_xo[((size_t)(b * NCn + (y2 >> 2) * WCn + (x2 >> 2))) * Cn + c];
                acc += w[(di + 1) * 3 + (dj + 1)] * v;
            }
        }
        size_t pix = ((size_t)(b * Hn + yy)) * Wn + xx;
        g_z[pix * Cn + c] = 0.5f * acc + 0.5f * g_yo[pix * Cn + c];
    }
}

// ---------------- K7: dwconv3x3(dw) on z -> z2 ----------------
__global__ __launch_bounds__(384) void dwconv2_kernel(
    const float* __restrict__ dww, const float* __restrict__ dwb)
{
    __shared__ float wsh[Cn * 9];
    __shared__ float bsh[Cn];
    int tid = threadIdx.x;
    for (int i = tid; i < Cn * 9; i += 384) wsh[i] = dww[i];
    bsh[tid] = dwb[tid];
    __syncthreads();

    int b  = blockIdx.x >> 6;
    int yy = blockIdx.x & 63;
    int c  = tid;
    const float* wc9 = &wsh[c * 9];
    float w[9];
#pragma unroll
    for (int i = 0; i < 9; i++) w[i] = wc9[i];

    for (int xx = 0; xx < Wn; xx++) {
        float acc = bsh[c];
#pragma unroll
        for (int di = -1; di <= 1; di++) {
            int y2 = yy + di;
            if (y2 < 0 || y2 >= Hn) continue;
#pragma unroll
            for (int dj = -1; dj <= 1; dj++) {
                int x2 = xx + dj;
                if (x2 < 0 || x2 >= Wn) continue;
                float v = g_z[(((size_t)(b * Hn + y2)) * Wn + x2) * Cn + c];
                acc += w[(di + 1) * 3 + (dj + 1)] * v;
            }
        }
        size_t pix = ((size_t)(b * Hn + yy)) * Wn + xx;
        g_z2[pix * Cn + c] = acc;
    }
}

// ---------------- launch ----------------
extern "C" void kernel_launch(void* const* d_in, const int* in_sizes, int n_in,
                              void* d_out, int out_size)
{
    const float* x     = (const float*)d_in[0];
    const float* qkv_w = (const float*)d_in[1];
    const float* dwx_w = (const float*)d_in[2];
    const float* dwx_b = (const float*)d_in[3];
    const float* dw_w  = (const float*)d_in[4];
    const float* dw_b  = (const float*)d_in[5];
    const float* pw_w  = (const float*)d_in[6];
    const float* pw_b  = (const float*)d_in[7];
    float* out = (float*)d_out;

    // 1) coarse pooling
    pool_kernel<<<Bn * NCn, Cn>>>(x);

    // 2) coarse QKV: (2048,1152,384)
    gemm_tn<<<dim3(C3n / 64, (Bn * NCn) / 64), 256>>>(
        nullptr, qkv_w, nullptr, nullptr, Bn * NCn, C3n, Cn, 0);

    // 3) coarse routing attention + top-k
    coarse_attn_kernel<<<Bn * NHd * NCn, 256>>>();

    // 4) fine QKV: (32768,1152,384)
    gemm_tn<<<dim3(C3n / 64, (Bn * HWn) / 64), 256>>>(
        x, qkv_w, nullptr, nullptr, Bn * HWn, C3n, Cn, 1);

    // 5) fine windowed attention (gather via top-k)
    fine_attn_kernel<<<Bn * NHd * NCn, 128>>>();

    // 6) upsample+dwconv(dwx)+mix
    dwmix_kernel<<<Bn * Hn, Cn>>>(dwx_w, dwx_b);

    // 7) dwconv(dw)
    dwconv2_kernel<<<Bn * Hn, Cn>>>(dw_w, dw_b);

    // 8) pointwise projection (+bias) -> out
    gemm_tn<<<dim3(Cn / 64, (Bn * HWn) / 64), 256>>>(
        nullptr, pw_w, pw_b, out, Bn * HWn, Cn, Cn, 2);
}

// round 3
// speedup vs baseline: 1.3084x; 1.3084x over previous
#include <cuda_runtime.h>
#include <cuda_bf16.h>
#include <float.h>
#include <stdint.h>

// Problem constants
#define Bn   8
#define Hn   64
#define Wn   64
#define Cn   384
#define NHd  8
#define Dh   48
#define NCn  256
#define HWn  4096
#define C3n  1152
#define SCALE 0.14433756729740643f

// ---------------- scratch (device globals; no allocation) ----------------
__device__ float g_xc  [Bn * NCn * Cn];
__device__ float g_qkvc[Bn * NCn * C3n];
__device__ int   g_topk[Bn * NHd * NCn * 4];
__device__ float g_xo  [Bn * NCn * Cn];
__device__ float g_qkvf[(size_t)Bn * HWn * C3n];
__device__ float g_yo  [(size_t)Bn * HWn * Cn];
__device__ float g_z   [(size_t)Bn * HWn * Cn];
__device__ float g_z2  [(size_t)Bn * HWn * Cn];
__device__ __nv_bfloat16 g_wqh[C3n * Cn];   // qkv W hi
__device__ __nv_bfloat16 g_wql[C3n * Cn];   // qkv W lo
__device__ __nv_bfloat16 g_wph[Cn * Cn];    // pw  W hi
__device__ __nv_bfloat16 g_wpl[Cn * Cn];    // pw  W lo

// ---------------- helpers ----------------
__device__ __forceinline__ uint32_t smem_u32(const void* p) {
    uint32_t a;
    asm("{ .reg .u64 t; cvta.to.shared.u64 t, %1; cvt.u32.u64 %0, t; }"
        : "=r"(a) : "l"(p));
    return a;
}
__device__ __forceinline__ void ldmx4(uint32_t* r, uint32_t addr) {
    asm volatile("ldmatrix.sync.aligned.m8n8.x4.shared.b16 {%0,%1,%2,%3}, [%4];"
        : "=r"(r[0]), "=r"(r[1]), "=r"(r[2]), "=r"(r[3]) : "r"(addr));
}
__device__ __forceinline__ void mma16816(float* d, const uint32_t* a, const uint32_t* b) {
    asm volatile(
        "mma.sync.aligned.m16n8k16.row.col.f32.bf16.bf16.f32 "
        "{%0,%1,%2,%3}, {%4,%5,%6,%7}, {%8,%9}, {%0,%1,%2,%3};"
        : "+f"(d[0]), "+f"(d[1]), "+f"(d[2]), "+f"(d[3])
        : "r"(a[0]), "r"(a[1]), "r"(a[2]), "r"(a[3]), "r"(b[0]), "r"(b[1]));
}
__device__ __forceinline__ uint32_t pack_bf2(float x, float y) {
    unsigned short hx = __bfloat16_as_ushort(__float2bfloat16(x));
    unsigned short hy = __bfloat16_as_ushort(__float2bfloat16(y));
    return (uint32_t)hx | ((uint32_t)hy << 16);
}

// ---------------- K1: 4x4 average pool ----------------
__global__ __launch_bounds__(384) void pool_kernel(const float* __restrict__ x)
{
    int blk = blockIdx.x;
    int n = blk & 255, b = blk >> 8;
    int hc = n >> 4, wc = n & 15;
    int c = threadIdx.x;
    float s = 0.f;
#pragma unroll
    for (int i = 0; i < 4; i++)
#pragma unroll
        for (int j = 0; j < 4; j++)
            s += x[(((size_t)(b * Hn + hc * 4 + i)) * Wn + wc * 4 + j) * Cn + c];
    g_xc[((size_t)(b * NCn + n)) * Cn + c] = s * 0.0625f;
}

// ---------------- weight split-bf16 conversion ----------------
// mode 0: qkv_w -> g_wqh/g_wql ; mode 1: pw_w -> g_wph/g_wpl
__global__ __launch_bounds__(256) void convw_kernel(
    const float* __restrict__ w, int total, int mode)
{
    int i = blockIdx.x * 256 + threadIdx.x;
    if (i >= total) return;
    float v = w[i];
    __nv_bfloat16 h = __float2bfloat16(v);
    __nv_bfloat16 l = __float2bfloat16(v - __bfloat162float(h));
    if (mode == 0) { g_wqh[i] = h; g_wql[i] = l; }
    else           { g_wph[i] = h; g_wpl[i] = l; }
}

// ---------------- tensor-core GEMM: O[M,N] = A[M,384] * W[N,384]^T --------
// split-bf16: acc = Ah*Wh + Al*Wh + Ah*Wl.  A converted in-kernel.
// 128x128 block tile, 512 threads (4x4 warps, 32x32 warp tile), BK=16.
// mode 0: A=g_xc -> g_qkvc (W=qkv)   mode 1: A=Aext -> g_qkvf (W=qkv)
// mode 2: A=g_z2 -> Oext (+bias, W=pw)
#define PITCH 24
__global__ __launch_bounds__(512) void gemm_mma(
    const float* __restrict__ Aext, const float* __restrict__ bias,
    float* __restrict__ Oext, int N, int mode)
{
    __shared__ __nv_bfloat16 sAh[128 * PITCH];
    __shared__ __nv_bfloat16 sAl[128 * PITCH];
    __shared__ __nv_bfloat16 sBh[128 * PITCH];
    __shared__ __nv_bfloat16 sBl[128 * PITCH];

    const float* A = (mode == 0) ? g_xc : (mode == 2) ? g_z2 : Aext;
    float*       O = (mode == 0) ? g_qkvc : (mode == 1) ? g_qkvf : Oext;
    const __nv_bfloat16* Wh = (mode == 2) ? g_wph : g_wqh;
    const __nv_bfloat16* Wl = (mode == 2) ? g_wpl : g_wql;

    int tid = threadIdx.x;
    int m0 = blockIdx.y * 128, n0 = blockIdx.x * 128;

    // staging assignment: thread -> (row 0..127, 4 consecutive k's)
    int srow = tid >> 2;
    int scol = (tid & 3) * 4;

    const float* aptr = A + (size_t)(m0 + srow) * 384 + scol;
    const __nv_bfloat16* whp = Wh + (size_t)(n0 + srow) * 384 + scol;
    const __nv_bfloat16* wlp = Wl + (size_t)(n0 + srow) * 384 + scol;

    // prefetch chunk 0
    float4 a4 = *(const float4*)aptr;
    uint2  wh = *(const uint2*)whp;
    uint2  wl = *(const uint2*)wlp;

    // warp tiling
    int lane = tid & 31;
    int wid = tid >> 5;
    int mbase = (wid & 3) * 32;
    int nbase = (wid >> 2) * 32;

    uint32_t bAh = smem_u32(sAh), bAl = smem_u32(sAl);
    uint32_t bBh = smem_u32(sBh), bBl = smem_u32(sBl);

    int ar = lane & 15, ak = (lane >> 4) * 8;
    uint32_t offA0 = ((mbase + ar) * PITCH + ak) * 2;
    uint32_t offA1 = offA0 + 16 * PITCH * 2;
    int br = (lane & 7) + ((lane >> 4) << 3), bk = ((lane >> 3) & 1) * 8;
    uint32_t offB0 = ((nbase + br) * PITCH + bk) * 2;
    uint32_t offB1 = offB0 + 16 * PITCH * 2;

    uint32_t sstore = (uint32_t)(srow * PITCH + scol) * 2;

    float acc[2][4][4];
#pragma unroll
    for (int i = 0; i < 2; i++)
#pragma unroll
        for (int j = 0; j < 4; j++)
#pragma unroll
            for (int k = 0; k < 4; k++) acc[i][j][k] = 0.f;

    for (int kc = 0; kc < 24; kc++) {
        __syncthreads();
        // convert A to hi/lo and store; copy W hi/lo
        {
            uint32_t h01 = pack_bf2(a4.x, a4.y);
            uint32_t h23 = pack_bf2(a4.z, a4.w);
            float hx = __bfloat162float(__float2bfloat16(a4.x));
            float hy = __bfloat162float(__float2bfloat16(a4.y));
            float hz = __bfloat162float(__float2bfloat16(a4.z));
            float hw = __bfloat162float(__float2bfloat16(a4.w));
            uint32_t l01 = pack_bf2(a4.x - hx, a4.y - hy);
            uint32_t l23 = pack_bf2(a4.z - hz, a4.w - hw);
            *(uint2*)((char*)sAh + sstore) = make_uint2(h01, h23);
            *(uint2*)((char*)sAl + sstore) = make_uint2(l01, l23);
            *(uint2*)((char*)sBh + sstore) = wh;
            *(uint2*)((char*)sBl + sstore) = wl;
        }
        __syncthreads();
        if (kc < 23) {
            a4 = *(const float4*)(aptr + (kc + 1) * 16);
            wh = *(const uint2*)(whp + (kc + 1) * 16);
            wl = *(const uint2*)(wlp + (kc + 1) * 16);
        }
        uint32_t ah[2][4], al[2][4], bh[2][4], bl[2][4];
        ldmx4(ah[0], bAh + offA0); ldmx4(ah[1], bAh + offA1);
        ldmx4(al[0], bAl + offA0); ldmx4(al[1], bAl + offA1);
        ldmx4(bh[0], bBh + offB0); ldmx4(bh[1], bBh + offB1);
        ldmx4(bl[0], bBl + offB0); ldmx4(bl[1], bBl + offB1);
#pragma unroll
        for (int mi = 0; mi < 2; mi++)
#pragma unroll
            for (int nj = 0; nj < 2; nj++)
#pragma unroll
                for (int sub = 0; sub < 2; sub++) {
                    float* d = acc[mi][nj * 2 + sub];
                    mma16816(d, ah[mi], &bh[nj][sub * 2]);
                    mma16816(d, al[mi], &bh[nj][sub * 2]);
                    mma16816(d, ah[mi], &bl[nj][sub * 2]);
                }
    }

    // epilogue
    int rbase = m0 + mbase, cbase = n0 + nbase;
#pragma unroll
    for (int mi = 0; mi < 2; mi++)
#pragma unroll
        for (int ni = 0; ni < 4; ni++) {
            int row = rbase + mi * 16 + (lane >> 2);
            int col = cbase + ni * 8 + (lane & 3) * 2;
            float b0 = 0.f, b1 = 0.f;
            if (mode == 2) { b0 = bias[col]; b1 = bias[col + 1]; }
            float2 v0 = make_float2(acc[mi][ni][0] + b0, acc[mi][ni][1] + b1);
            float2 v1 = make_float2(acc[mi][ni][2] + b0, acc[mi][ni][3] + b1);
            *(float2*)&O[(size_t)row * N + col] = v0;
            *(float2*)&O[(size_t)(row + 8) * N + col] = v1;
        }
}

// ---------------- K3: coarse routing attention + top-k ----------------
__global__ __launch_bounds__(256) void coarse_attn_kernel()
{
    int bid = blockIdx.x;
    int q  = bid & 255;
    int hd = (bid >> 8) & 7;
    int b  = bid >> 11;

    __shared__ float logits[256];
    __shared__ float red[256];
    __shared__ int   redi[256];
    __shared__ float qv[Dh];
    __shared__ float part[4][Dh];
    __shared__ float s_max, s_inv;

    int tid = threadIdx.x;
    const float* base = g_qkvc + (size_t)b * NCn * C3n;

    if (tid < Dh) qv[tid] = base[(size_t)q * C3n + hd * Dh + tid];
    __syncthreads();

    const float* krow = base + (size_t)tid * C3n + Cn + hd * Dh;
    float s = 0.f;
#pragma unroll
    for (int dd = 0; dd < Dh; dd++) s += qv[dd] * krow[dd];
    s *= SCALE;
    logits[tid] = s;

    float work = s;
    for (int t = 0; t < 4; t++) {
        red[tid] = work; redi[tid] = tid;
        __syncthreads();
        for (int off = 128; off > 0; off >>= 1) {
            if (tid < off) {
                float ov = red[tid + off];
                int   oi = redi[tid + off];
                if (ov > red[tid] || (ov == red[tid] && oi < redi[tid])) {
                    red[tid] = ov; redi[tid] = oi;
                }
            }
            __syncthreads();
        }
        if (tid == 0) {
            g_topk[(size_t)bid * 4 + t] = redi[0];
            if (t == 0) s_max = red[0];
        }
        __syncthreads();
        if (tid == redi[0]) work = -FLT_MAX;
        __syncthreads();
    }

    float p = __expf(logits[tid] - s_max);
    red[tid] = p;
    __syncthreads();
    for (int off = 128; off > 0; off >>= 1) {
        if (tid < off) red[tid] += red[tid + off];
        __syncthreads();
    }
    if (tid == 0) s_inv = 1.f / red[0];
    __syncthreads();
    logits[tid] = p * s_inv;
    __syncthreads();

    int g = tid / Dh, dd = tid % Dh;
    if (g < 4) {
        const float* vb = base + Cn * 2 + hd * Dh + dd;
        float acc = 0.f;
        int j0 = g * 64;
#pragma unroll 4
        for (int j = j0; j < j0 + 64; j++)
            acc += logits[j] * vb[(size_t)j * C3n];
        part[g][dd] = acc;
    }
    __syncthreads();
    if (tid < Dh) {
        float rr = part[0][tid] + part[1][tid] + part[2][tid] + part[3][tid];
        g_xo[((size_t)(b * NCn + q)) * Cn + hd * Dh + tid] = rr;
    }
}

// ---------------- K5: fine windowed attention ----------------
__global__ __launch_bounds__(128) void fine_attn_kernel()
{
    int bid = blockIdx.x;
    int n  = bid & 255;
    int hd = (bid >> 8) & 7;
    int b  = bid >> 11;

    __shared__ float Qs[16][49];
    __shared__ float Ks[64][49];
    __shared__ float Vs[64][49];
    __shared__ float A2[16][64];
    __shared__ int   wins[4];

    int tid = threadIdx.x;
    int hc = n >> 4, wc = n & 15;
    const float* base = g_qkvf + (size_t)b * HWn * C3n;

    if (tid < 4) wins[tid] = g_topk[(size_t)bid * 4 + tid];

    for (int idx = tid; idx < 16 * Dh; idx += 128) {
        int p = idx / Dh, dd = idx % Dh;
        int s = (hc * 4 + (p >> 2)) * Wn + wc * 4 + (p & 3);
        Qs[p][dd] = base[(size_t)s * C3n + hd * Dh + dd];
    }
    __syncthreads();

    for (int idx = tid; idx < 64 * Dh; idx += 128) {
        int p = idx / Dh, dd = idx % Dh;
        int t = p >> 4, pl = p & 15;
        int m = wins[t];
        int s = ((m >> 4) * 4 + (pl >> 2)) * Wn + (m & 15) * 4 + (pl & 3);
        const float* row = base + (size_t)s * C3n + hd * Dh + dd;
        Ks[p][dd] = row[Cn];
        Vs[p][dd] = row[2 * Cn];
    }
    __syncthreads();

    for (int idx = tid; idx < 16 * 64; idx += 128) {
        int qq = idx >> 6, kk = idx & 63;
        float s = 0.f;
#pragma unroll
        for (int dd = 0; dd < Dh; dd++) s += Qs[qq][dd] * Ks[kk][dd];
        A2[qq][kk] = s * SCALE;
    }
    __syncthreads();

    if (tid < 16) {
        float m = -FLT_MAX;
#pragma unroll
        for (int kk = 0; kk < 64; kk++) m = fmaxf(m, A2[tid][kk]);
        float sum = 0.f;
#pragma unroll
        for (int kk = 0; kk < 64; kk++) {
            float e = __expf(A2[tid][kk] - m);
            A2[tid][kk] = e; sum += e;
        }
        float inv = 1.f / sum;
#pragma unroll
        for (int kk = 0; kk < 64; kk++) A2[tid][kk] *= inv;
    }
    __syncthreads();

    for (int idx = tid; idx < 16 * Dh; idx += 128) {
        int p = idx / Dh, dd = idx % Dh;
        float acc = 0.f;
#pragma unroll
        for (int kk = 0; kk < 64; kk++) acc += A2[p][kk] * Vs[kk][dd];
        int yy = hc * 4 + (p >> 2), xx = wc * 4 + (p & 3);
        g_yo[(((size_t)(b * Hn + yy)) * Wn + xx) * Cn + hd * Dh + dd] = acc;
    }
}

// ---------------- K6: upsample(xo) -> dwconv3x3(dwx) -> mix with yo -------
__global__ __launch_bounds__(384) void dwmix_kernel(
    const float* __restrict__ dwxw, const float* __restrict__ dwxb)
{
    __shared__ float wsh[Cn * 9];
    int tid = threadIdx.x;
    for (int i = tid; i < Cn * 9; i += 384) wsh[i] = dwxw[i];
    __syncthreads();

    int b  = blockIdx.x >> 6;
    int yy = blockIdx.x & 63;
    int c  = tid;
    float w[9];
#pragma unroll
    for (int i = 0; i < 9; i++) w[i] = wsh[c * 9 + i];
    float bias = dwxb[c];

    const float* xob = g_xo + (size_t)b * NCn * Cn + c;
    bool up = yy > 0, dn = yy < 63;
    int ru = (yy - 1) >> 2, rm = yy >> 2, rd = (yy + 1) >> 2;

    float3 cm = make_float3(0.f, 0.f, 0.f), cc, cp;
    cc.x = up ? xob[(size_t)(ru * 16) * Cn] : 0.f;
    cc.y = xob[(size_t)(rm * 16) * Cn];
    cc.z = dn ? xob[(size_t)(rd * 16) * Cn] : 0.f;

    size_t pix0 = ((size_t)(b * Hn + yy)) * Wn;
    for (int xx = 0; xx < 64; xx++) {
        if (xx < 63) {
            int xc4 = (xx + 1) >> 2;
            cp.x = up ? xob[(size_t)(ru * 16 + xc4) * Cn] : 0.f;
            cp.y = xob[(size_t)(rm * 16 + xc4) * Cn];
            cp.z = dn ? xob[(size_t)(rd * 16 + xc4) * Cn] : 0.f;
        } else {
            cp = make_float3(0.f, 0.f, 0.f);
        }
        float acc = bias
            + w[0] * cm.x + w[1] * cc.x + w[2] * cp.x
            + w[3] * cm.y + w[4] * cc.y + w[5] * cp.y
            + w[6] * cm.z + w[7] * cc.z + w[8] * cp.z;
        size_t pix = pix0 + xx;
        g_z[pix * Cn + c] = 0.5f * acc + 0.5f * g_yo[pix * Cn + c];
        cm = cc; cc = cp;
    }
}

// ---------------- K7: dwconv3x3(dw) on z -> z2 ----------------
__global__ __launch_bounds__(384) void dwconv2_kernel(
    const float* __restrict__ dww, const float* __restrict__ dwb)
{
    __shared__ float wsh[Cn * 9];
    int tid = threadIdx.x;
    for (int i = tid; i < Cn * 9; i += 384) wsh[i] = dww[i];
    __syncthreads();

    int b  = blockIdx.x >> 6;
    int yy = blockIdx.x & 63;
    int c  = tid;
    float w[9];
#pragma unroll
    for (int i = 0; i < 9; i++) w[i] = wsh[c * 9 + i];
    float bias = dwb[c];

    const float* zb = g_z + (size_t)b * HWn * Cn + c;
    bool up = yy > 0, dn = yy < 63;
    size_t rowm = (size_t)yy * Wn;

    float3 cm = make_float3(0.f, 0.f, 0.f), cc, cp;
    cc.x = up ? zb[(rowm - Wn) * Cn] : 0.f;
    cc.y = zb[rowm * Cn];
    cc.z = dn ? zb[(rowm + Wn) * Cn] : 0.f;

    float* out = g_z2 + ((size_t)b * HWn + rowm) * Cn + c;
    for (int xx = 0; xx < 64; xx++) {
        if (xx < 63) {
            size_t bcol = rowm + xx + 1;
            cp.x = up ? zb[(bcol - Wn) * Cn] : 0.f;
            cp.y = zb[bcol * Cn];
            cp.z = dn ? zb[(bcol + Wn) * Cn] : 0.f;
        } else {
            cp = make_float3(0.f, 0.f, 0.f);
        }
        float acc = bias
            + w[0] * cm.x + w[1] * cc.x + w[2] * cp.x
            + w[3] * cm.y + w[4] * cc.y + w[5] * cp.y
            + w[6] * cm.z + w[7] * cc.z + w[8] * cp.z;
        out[(size_t)xx * Cn] = acc;
        cm = cc; cc = cp;
    }
}

// ---------------- launch ----------------
extern "C" void kernel_launch(void* const* d_in, const int* in_sizes, int n_in,
                              void* d_out, int out_size)
{
    const float* x     = (const float*)d_in[0];
    const float* qkv_w = (const float*)d_in[1];
    const float* dwx_w = (const float*)d_in[2];
    const float* dwx_b = (const float*)d_in[3];
    const float* dw_w  = (const float*)d_in[4];
    const float* dw_b  = (const float*)d_in[5];
    const float* pw_w  = (const float*)d_in[6];
    const float* pw_b  = (const float*)d_in[7];
    float* out = (float*)d_out;

    // weight conversions (tiny)
    convw_kernel<<<(C3n * Cn + 255) / 256, 256>>>(qkv_w, C3n * Cn, 0);
    convw_kernel<<<(Cn * Cn + 255) / 256, 256>>>(pw_w, Cn * Cn, 1);

    // 1) coarse pooling
    pool_kernel<<<Bn * NCn, Cn>>>(x);

    // 2) coarse QKV: (2048 x 1152 x 384)
    gemm_mma<<<dim3(C3n / 128, (Bn * NCn) / 128), 512>>>(
        nullptr, nullptr, nullptr, C3n, 0);

    // 3) coarse routing attention + top-k
    coarse_attn_kernel<<<Bn * NHd * NCn, 256>>>();

    // 4) fine QKV: (32768 x 1152 x 384)
    gemm_mma<<<dim3(C3n / 128, (Bn * HWn) / 128), 512>>>(
        x, nullptr, nullptr, C3n, 1);

    // 5) fine windowed attention
    fine_attn_kernel<<<Bn * NHd * NCn, 128>>>();

    // 6) upsample+dwconv(dwx)+mix
    dwmix_kernel<<<Bn * Hn, Cn>>>(dwx_w, dwx_b);

    // 7) dwconv(dw)
    dwconv2_kernel<<<Bn * Hn, Cn>>>(dw_w, dw_b);

    // 8) pointwise projection (+bias): (32768 x 384 x 384)
    gemm_mma<<<dim3(Cn / 128, (Bn * HWn) / 128), 512>>>(
        nullptr, pw_b, out, Cn, 2);
}

// round 4
// speedup vs baseline: 1.5309x; 1.1701x over previous
#include <cuda_runtime.h>
#include <cuda_bf16.h>
#include <float.h>
#include <stdint.h>

// Problem constants
#define Bn   8
#define Hn   64
#define Wn   64
#define Cn   384
#define NHd  8
#define Dh   48
#define NCn  256
#define HWn  4096
#define C3n  1152
#define SCALE 0.14433756729740643f

// ---------------- scratch (device globals; no allocation) ----------------
__device__ float g_xc  [Bn * NCn * Cn];
__device__ float g_qkvc[Bn * NCn * C3n];
__device__ int   g_topk[Bn * NHd * NCn * 4];
__device__ float g_xo  [Bn * NCn * Cn];
__device__ float g_qkvf[(size_t)Bn * HWn * C3n];
__device__ float g_yo  [(size_t)Bn * HWn * Cn];
__device__ float g_z   [(size_t)Bn * HWn * Cn];
__device__ float g_z2  [(size_t)Bn * HWn * Cn];
__device__ __nv_bfloat16 g_wqh[C3n * Cn];   // qkv W hi
__device__ __nv_bfloat16 g_wql[C3n * Cn];   // qkv W lo
__device__ __nv_bfloat16 g_wph[Cn * Cn];    // pw  W hi
__device__ __nv_bfloat16 g_wpl[Cn * Cn];    // pw  W lo

// ---------------- helpers ----------------
__device__ __forceinline__ uint32_t smem_u32(const void* p) {
    uint32_t a;
    asm("{ .reg .u64 t; cvta.to.shared.u64 t, %1; cvt.u32.u64 %0, t; }"
        : "=r"(a) : "l"(p));
    return a;
}
__device__ __forceinline__ void ldmx4(uint32_t* r, uint32_t addr) {
    asm volatile("ldmatrix.sync.aligned.m8n8.x4.shared.b16 {%0,%1,%2,%3}, [%4];"
        : "=r"(r[0]), "=r"(r[1]), "=r"(r[2]), "=r"(r[3]) : "r"(addr));
}
__device__ __forceinline__ void mma16816(float* d, const uint32_t* a, const uint32_t* b) {
    asm volatile(
        "mma.sync.aligned.m16n8k16.row.col.f32.bf16.bf16.f32 "
        "{%0,%1,%2,%3}, {%4,%5,%6,%7}, {%8,%9}, {%0,%1,%2,%3};"
        : "+f"(d[0]), "+f"(d[1]), "+f"(d[2]), "+f"(d[3])
        : "r"(a[0]), "r"(a[1]), "r"(a[2]), "r"(a[3]), "r"(b[0]), "r"(b[1]));
}
__device__ __forceinline__ uint32_t pack_bf2(float x, float y) {
    unsigned short hx = __bfloat16_as_ushort(__float2bfloat16(x));
    unsigned short hy = __bfloat16_as_ushort(__float2bfloat16(y));
    return (uint32_t)hx | ((uint32_t)hy << 16);
}

// ---------------- K1: 4x4 average pool ----------------
__global__ __launch_bounds__(384) void pool_kernel(const float* __restrict__ x)
{
    int blk = blockIdx.x;
    int n = blk & 255, b = blk >> 8;
    int hc = n >> 4, wc = n & 15;
    int c = threadIdx.x;
    float s = 0.f;
#pragma unroll
    for (int i = 0; i < 4; i++)
#pragma unroll
        for (int j = 0; j < 4; j++)
            s += x[(((size_t)(b * Hn + hc * 4 + i)) * Wn + wc * 4 + j) * Cn + c];
    g_xc[((size_t)(b * NCn + n)) * Cn + c] = s * 0.0625f;
}

// ---------------- weight split-bf16 conversion ----------------
__global__ __launch_bounds__(256) void convw_kernel(
    const float* __restrict__ w, int total, int mode)
{
    int i = blockIdx.x * 256 + threadIdx.x;
    if (i >= total) return;
    float v = w[i];
    __nv_bfloat16 h = __float2bfloat16(v);
    __nv_bfloat16 l = __float2bfloat16(v - __bfloat162float(h));
    if (mode == 0) { g_wqh[i] = h; g_wql[i] = l; }
    else           { g_wph[i] = h; g_wpl[i] = l; }
}

// ---------------- tensor-core GEMM: O[M,N] = A[M,384] * W[N,384]^T --------
// split-bf16: acc = Ah*Wh + Al*Wh + Ah*Wl.  A converted in-kernel.
// 128x128 block tile, 512 threads, BK=16, double-buffered smem.
#define PITCH 24
#define PLANE 3072                 // elems per plane (128*24)
#define BUFEL (4 * PLANE)          // elems per buffer
#define AHOFF 0
#define ALOFF (PLANE * 2)          // byte offsets
#define BHOFF (PLANE * 4)
#define BLOFF (PLANE * 6)
#define GEMM_SMEM (2 * BUFEL * 2)  // bytes = 49152

__global__ __launch_bounds__(512) void gemm_mma(
    const float* __restrict__ Aext, const float* __restrict__ bias,
    float* __restrict__ Oext, int N, int mode)
{
    extern __shared__ __nv_bfloat16 sm[];

    const float* A = (mode == 0) ? g_xc : (mode == 2) ? g_z2 : Aext;
    float*       O = (mode == 0) ? g_qkvc : (mode == 1) ? g_qkvf : Oext;
    const __nv_bfloat16* Wh = (mode == 2) ? g_wph : g_wqh;
    const __nv_bfloat16* Wl = (mode == 2) ? g_wpl : g_wql;

    int tid = threadIdx.x;
    int m0 = blockIdx.y * 128, n0 = blockIdx.x * 128;

    int srow = tid >> 2;
    int scol = (tid & 3) * 4;

    const float* aptr = A + (size_t)(m0 + srow) * 384 + scol;
    const __nv_bfloat16* whp = Wh + (size_t)(n0 + srow) * 384 + scol;
    const __nv_bfloat16* wlp = Wl + (size_t)(n0 + srow) * 384 + scol;

    int lane = tid & 31;
    int wid = tid >> 5;
    int mbase = (wid & 3) * 32;
    int nbase = (wid >> 2) * 32;

    uint32_t sbase = smem_u32(sm);

    int ar = lane & 15, ak = (lane >> 4) * 8;
    uint32_t offA0 = ((mbase + ar) * PITCH + ak) * 2;
    uint32_t offA1 = offA0 + 16 * PITCH * 2;
    int br = (lane & 7) + ((lane >> 4) << 3), bk = ((lane >> 3) & 1) * 8;
    uint32_t offB0 = ((nbase + br) * PITCH + bk) * 2;
    uint32_t offB1 = offB0 + 16 * PITCH * 2;

    int sidx = srow * PITCH + scol;

    float acc[2][4][4];
#pragma unroll
    for (int i = 0; i < 2; i++)
#pragma unroll
        for (int j = 0; j < 4; j++)
#pragma unroll
            for (int k = 0; k < 4; k++) acc[i][j][k] = 0.f;

    // prologue: stage chunk 0 into buffer 0
    {
        float4 a4 = *(const float4*)aptr;
        uint2  wh = *(const uint2*)whp;
        uint2  wl = *(const uint2*)wlp;
        uint32_t h01 = pack_bf2(a4.x, a4.y);
        uint32_t h23 = pack_bf2(a4.z, a4.w);
        float hx = __bfloat162float(__float2bfloat16(a4.x));
        float hy = __bfloat162float(__float2bfloat16(a4.y));
        float hz = __bfloat162float(__float2bfloat16(a4.z));
        float hw = __bfloat162float(__float2bfloat16(a4.w));
        uint32_t l01 = pack_bf2(a4.x - hx, a4.y - hy);
        uint32_t l23 = pack_bf2(a4.z - hz, a4.w - hw);
        *(uint2*)(sm + 0 * BUFEL + 0 * PLANE + sidx) = make_uint2(h01, h23);
        *(uint2*)(sm + 0 * BUFEL + 1 * PLANE + sidx) = make_uint2(l01, l23);
        *(uint2*)(sm + 0 * BUFEL + 2 * PLANE + sidx) = wh;
        *(uint2*)(sm + 0 * BUFEL + 3 * PLANE + sidx) = wl;
    }
    __syncthreads();

    for (int kc = 0; kc < 24; kc++) {
        int cur = kc & 1;
        float4 a4n; uint2 whn, wln;
        if (kc < 23) {
            a4n = *(const float4*)(aptr + (kc + 1) * 16);
            whn = *(const uint2*)(whp + (kc + 1) * 16);
            wln = *(const uint2*)(wlp + (kc + 1) * 16);
        }

        uint32_t bb = sbase + (uint32_t)cur * (BUFEL * 2);
        uint32_t ah[2][4], al[2][4], bh[2][4], bl[2][4];
        ldmx4(ah[0], bb + AHOFF + offA0); ldmx4(ah[1], bb + AHOFF + offA1);
        ldmx4(al[0], bb + ALOFF + offA0); ldmx4(al[1], bb + ALOFF + offA1);
        ldmx4(bh[0], bb + BHOFF + offB0); ldmx4(bh[1], bb + BHOFF + offB1);
        ldmx4(bl[0], bb + BLOFF + offB0); ldmx4(bl[1], bb + BLOFF + offB1);
#pragma unroll
        for (int mi = 0; mi < 2; mi++)
#pragma unroll
            for (int nj = 0; nj < 2; nj++)
#pragma unroll
                for (int sub = 0; sub < 2; sub++) {
                    float* d = acc[mi][nj * 2 + sub];
                    mma16816(d, ah[mi], &bh[nj][sub * 2]);
                    mma16816(d, al[mi], &bh[nj][sub * 2]);
                    mma16816(d, ah[mi], &bl[nj][sub * 2]);
                }

        if (kc < 23) {
            int nb = cur ^ 1;
            uint32_t h01 = pack_bf2(a4n.x, a4n.y);
            uint32_t h23 = pack_bf2(a4n.z, a4n.w);
            float hx = __bfloat162float(__float2bfloat16(a4n.x));
            float hy = __bfloat162float(__float2bfloat16(a4n.y));
            float hz = __bfloat162float(__float2bfloat16(a4n.z));
            float hw = __bfloat162float(__float2bfloat16(a4n.w));
            uint32_t l01 = pack_bf2(a4n.x - hx, a4n.y - hy);
            uint32_t l23 = pack_bf2(a4n.z - hz, a4n.w - hw);
            *(uint2*)(sm + nb * BUFEL + 0 * PLANE + sidx) = make_uint2(h01, h23);
            *(uint2*)(sm + nb * BUFEL + 1 * PLANE + sidx) = make_uint2(l01, l23);
            *(uint2*)(sm + nb * BUFEL + 2 * PLANE + sidx) = whn;
            *(uint2*)(sm + nb * BUFEL + 3 * PLANE + sidx) = wln;
        }
        __syncthreads();
    }

    // epilogue
    int rbase = m0 + mbase, cbase = n0 + nbase;
#pragma unroll
    for (int mi = 0; mi < 2; mi++)
#pragma unroll
        for (int ni = 0; ni < 4; ni++) {
            int row = rbase + mi * 16 + (lane >> 2);
            int col = cbase + ni * 8 + (lane & 3) * 2;
            float b0 = 0.f, b1 = 0.f;
            if (mode == 2) { b0 = bias[col]; b1 = bias[col + 1]; }
            float2 v0 = make_float2(acc[mi][ni][0] + b0, acc[mi][ni][1] + b1);
            float2 v1 = make_float2(acc[mi][ni][2] + b0, acc[mi][ni][3] + b1);
            *(float2*)&O[(size_t)row * N + col] = v0;
            *(float2*)&O[(size_t)(row + 8) * N + col] = v1;
        }
}

// ---------------- K3: coarse routing attention + top-k ----------------
__global__ __launch_bounds__(256) void coarse_attn_kernel()
{
    int bid = blockIdx.x;
    int q  = bid & 255;
    int hd = (bid >> 8) & 7;
    int b  = bid >> 11;

    __shared__ float logits[256];
    __shared__ float red[256];
    __shared__ int   redi[256];
    __shared__ float qv[Dh];
    __shared__ float part[4][Dh];
    __shared__ float s_max, s_inv;

    int tid = threadIdx.x;
    const float* base = g_qkvc + (size_t)b * NCn * C3n;

    if (tid < Dh) qv[tid] = base[(size_t)q * C3n + hd * Dh + tid];
    __syncthreads();

    const float* krow = base + (size_t)tid * C3n + Cn + hd * Dh;
    float s = 0.f;
#pragma unroll
    for (int dd = 0; dd < Dh; dd++) s += qv[dd] * krow[dd];
    s *= SCALE;
    logits[tid] = s;

    float work = s;
    for (int t = 0; t < 4; t++) {
        red[tid] = work; redi[tid] = tid;
        __syncthreads();
        for (int off = 128; off > 0; off >>= 1) {
            if (tid < off) {
                float ov = red[tid + off];
                int   oi = redi[tid + off];
                if (ov > red[tid] || (ov == red[tid] && oi < redi[tid])) {
                    red[tid] = ov; redi[tid] = oi;
                }
            }
            __syncthreads();
        }
        if (tid == 0) {
            g_topk[(size_t)bid * 4 + t] = redi[0];
            if (t == 0) s_max = red[0];
        }
        __syncthreads();
        if (tid == redi[0]) work = -FLT_MAX;
        __syncthreads();
    }

    float p = __expf(logits[tid] - s_max);
    red[tid] = p;
    __syncthreads();
    for (int off = 128; off > 0; off >>= 1) {
        if (tid < off) red[tid] += red[tid + off];
        __syncthreads();
    }
    if (tid == 0) s_inv = 1.f / red[0];
    __syncthreads();
    logits[tid] = p * s_inv;
    __syncthreads();

    int g = tid / Dh, dd = tid % Dh;
    if (g < 4) {
        const float* vb = base + Cn * 2 + hd * Dh + dd;
        float acc = 0.f;
        int j0 = g * 64;
#pragma unroll 4
        for (int j = j0; j < j0 + 64; j++)
            acc += logits[j] * vb[(size_t)j * C3n];
        part[g][dd] = acc;
    }
    __syncthreads();
    if (tid < Dh) {
        float rr = part[0][tid] + part[1][tid] + part[2][tid] + part[3][tid];
        g_xo[((size_t)(b * NCn + q)) * Cn + hd * Dh + tid] = rr;
    }
}

// ---------------- K5: fine windowed attention (register-tiled) ------------
#define QT_P 18
#define KT_P 68
#define VS_P 49
#define A2_P 68
__global__ __launch_bounds__(128) void fine_attn_kernel()
{
    int bid = blockIdx.x;
    int n  = bid & 255;
    int hd = (bid >> 8) & 7;
    int b  = bid >> 11;

    __shared__ float Qt[48 * QT_P];   // Qt[dd][p], p<16
    __shared__ float Kt[48 * KT_P];   // Kt[dd][kk], kk<64
    __shared__ float Vs[64 * VS_P];   // Vs[kk][dd]
    __shared__ float A2[16 * A2_P];   // A2[p][kk]
    __shared__ int   wins[4];

    int tid = threadIdx.x;
    int hc = n >> 4, wc = n & 15;
    const float* base = g_qkvf + (size_t)b * HWn * C3n;

    if (tid < 4) wins[tid] = g_topk[(size_t)bid * 4 + tid];

    // stage Q (transposed): 16*48 elems
    for (int idx = tid; idx < 16 * Dh; idx += 128) {
        int p = idx / Dh, dd = idx % Dh;
        int s = (hc * 4 + (p >> 2)) * Wn + wc * 4 + (p & 3);
        Qt[dd * QT_P + p] = base[(size_t)s * C3n + hd * Dh + dd];
    }
    __syncthreads();  // wins visible

    // stage K (transposed) and V
    for (int idx = tid; idx < 64 * Dh; idx += 128) {
        int p = idx / Dh, dd = idx % Dh;
        int t = p >> 4, pl = p & 15;
        int m = wins[t];
        int s = ((m >> 4) * 4 + (pl >> 2)) * Wn + (m & 15) * 4 + (pl & 3);
        const float* row = base + (size_t)s * C3n + hd * Dh + dd;
        Kt[dd * KT_P + p] = row[Cn];
        Vs[p * VS_P + dd] = row[2 * Cn];
    }
    __syncthreads();

    // QK^T: 16x64 outputs; thread (tr= tid>>4, tc= tid&15) computes 2x4
    {
        int tr = tid >> 4, tc = tid & 15;
        int r0 = tr * 2, c0 = tc * 4;
        float a0[4] = {0.f, 0.f, 0.f, 0.f};
        float a1[4] = {0.f, 0.f, 0.f, 0.f};
#pragma unroll 8
        for (int dd = 0; dd < Dh; dd++) {
            float2 qv = *(const float2*)&Qt[dd * QT_P + r0];
            float4 kv = *(const float4*)&Kt[dd * KT_P + c0];
            a0[0] += qv.x * kv.x; a0[1] += qv.x * kv.y;
            a0[2] += qv.x * kv.z; a0[3] += qv.x * kv.w;
            a1[0] += qv.y * kv.x; a1[1] += qv.y * kv.y;
            a1[2] += qv.y * kv.z; a1[3] += qv.y * kv.w;
        }
        float4 w0 = make_float4(a0[0] * SCALE, a0[1] * SCALE, a0[2] * SCALE, a0[3] * SCALE);
        float4 w1 = make_float4(a1[0] * SCALE, a1[1] * SCALE, a1[2] * SCALE, a1[3] * SCALE);
        *(float4*)&A2[r0 * A2_P + c0] = w0;
        *(float4*)&A2[(r0 + 1) * A2_P + c0] = w1;
    }
    __syncthreads();

    // softmax: 8 threads per row, 8 cols each
    {
        int row = tid >> 3, j = tid & 7;
        float* ap = &A2[row * A2_P + j * 8];
        float v[8];
        float mx = -FLT_MAX;
#pragma unroll
        for (int i = 0; i < 8; i++) { v[i] = ap[i]; mx = fmaxf(mx, v[i]); }
#pragma unroll
        for (int m = 1; m < 8; m <<= 1)
            mx = fmaxf(mx, __shfl_xor_sync(0xffffffffu, mx, m));
        float sum = 0.f;
#pragma unroll
        for (int i = 0; i < 8; i++) { v[i] = __expf(v[i] - mx); sum += v[i]; }
#pragma unroll
        for (int m = 1; m < 8; m <<= 1)
            sum += __shfl_xor_sync(0xffffffffu, sum, m);
        float inv = 1.f / sum;
#pragma unroll
        for (int i = 0; i < 8; i++) ap[i] = v[i] * inv;
    }
    __syncthreads();

    // AV: 16x48 outputs; thread (tr2 = tid>>4, tc2 = tid&15) computes 2x3
    {
        int tr2 = tid >> 4, tc2 = tid & 15;
        int p0 = tr2 * 2, dd0 = tc2 * 3;
        float o0[3] = {0.f, 0.f, 0.f};
        float o1[3] = {0.f, 0.f, 0.f};
#pragma unroll 8
        for (int kk = 0; kk < 64; kk++) {
            float av0 = A2[p0 * A2_P + kk];
            float av1 = A2[(p0 + 1) * A2_P + kk];
            const float* vp = &Vs[kk * VS_P + dd0];
            float v0 = vp[0], v1 = vp[1], v2 = vp[2];
            o0[0] += av0 * v0; o0[1] += av0 * v1; o0[2] += av0 * v2;
            o1[0] += av1 * v0; o1[1] += av1 * v1; o1[2] += av1 * v2;
        }
#pragma unroll
        for (int pi = 0; pi < 2; pi++) {
            int p = p0 + pi;
            int yy = hc * 4 + (p >> 2), xx = wc * 4 + (p & 3);
            float* op = &g_yo[(((size_t)(b * Hn + yy)) * Wn + xx) * Cn + hd * Dh + dd0];
            if (pi == 0) { op[0] = o0[0]; op[1] = o0[1]; op[2] = o0[2]; }
            else         { op[0] = o1[0]; op[1] = o1[1]; op[2] = o1[2]; }
        }
    }
}

// ---------------- K6: upsample(xo) -> dwconv3x3(dwx) -> mix with yo -------
__global__ __launch_bounds__(384) void dwmix_kernel(
    const float* __restrict__ dwxw, const float* __restrict__ dwxb)
{
    __shared__ float wsh[Cn * 9];
    int tid = threadIdx.x;
    for (int i = tid; i < Cn * 9; i += 384) wsh[i] = dwxw[i];
    __syncthreads();

    int b  = blockIdx.x >> 6;
    int yy = blockIdx.x & 63;
    int c  = tid;
    float w[9];
#pragma unroll
    for (int i = 0; i < 9; i++) w[i] = wsh[c * 9 + i];
    float bias = dwxb[c];

    const float* xob = g_xo + (size_t)b * NCn * Cn + c;
    bool up = yy > 0, dn = yy < 63;
    int ru = (yy - 1) >> 2, rm = yy >> 2, rd = (yy + 1) >> 2;

    float3 cm = make_float3(0.f, 0.f, 0.f), cc, cp;
    cc.x = up ? xob[(size_t)(ru * 16) * Cn] : 0.f;
    cc.y = xob[(size_t)(rm * 16) * Cn];
    cc.z = dn ? xob[(size_t)(rd * 16) * Cn] : 0.f;

    size_t pix0 = ((size_t)(b * Hn + yy)) * Wn;
    for (int xx = 0; xx < 64; xx++) {
        if (xx < 63) {
            int xc4 = (xx + 1) >> 2;
            cp.x = up ? xob[(size_t)(ru * 16 + xc4) * Cn] : 0.f;
            cp.y = xob[(size_t)(rm * 16 + xc4) * Cn];
            cp.z = dn ? xob[(size_t)(rd * 16 + xc4) * Cn] : 0.f;
        } else {
            cp = make_float3(0.f, 0.f, 0.f);
        }
        float acc = bias
            + w[0] * cm.x + w[1] * cc.x + w[2] * cp.x
            + w[3] * cm.y + w[4] * cc.y + w[5] * cp.y
            + w[6] * cm.z + w[7] * cc.z + w[8] * cp.z;
        size_t pix = pix0 + xx;
        g_z[pix * Cn + c] = 0.5f * acc + 0.5f * g_yo[pix * Cn + c];
        cm = cc; cc = cp;
    }
}

// ---------------- K7: dwconv3x3(dw) on z -> z2 ----------------
__global__ __launch_bounds__(384) void dwconv2_kernel(
    const float* __restrict__ dww, const float* __restrict__ dwb)
{
    __shared__ float wsh[Cn * 9];
    int tid = threadIdx.x;
    for (int i = tid; i < Cn * 9; i += 384) wsh[i] = dww[i];
    __syncthreads();

    int b  = blockIdx.x >> 6;
    int yy = blockIdx.x & 63;
    int c  = tid;
    float w[9];
#pragma unroll
    for (int i = 0; i < 9; i++) w[i] = wsh[c * 9 + i];
    float bias = dwb[c];

    const float* zb = g_z + (size_t)b * HWn * Cn + c;
    bool up = yy > 0, dn = yy < 63;
    size_t rowm = (size_t)yy * Wn;

    float3 cm = make_float3(0.f, 0.f, 0.f), cc, cp;
    cc.x = up ? zb[(rowm - Wn) * Cn] : 0.f;
    cc.y = zb[rowm * Cn];
    cc.z = dn ? zb[(rowm + Wn) * Cn] : 0.f;

    float* out = g_z2 + ((size_t)b * HWn + rowm) * Cn + c;
    for (int xx = 0; xx < 64; xx++) {
        if (xx < 63) {
            size_t bcol = rowm + xx + 1;
            cp.x = up ? zb[(bcol - Wn) * Cn] : 0.f;
            cp.y = zb[bcol * Cn];
            cp.z = dn ? zb[(bcol + Wn) * Cn] : 0.f;
        } else {
            cp = make_float3(0.f, 0.f, 0.f);
        }
        float acc = bias
            + w[0] * cm.x + w[1] * cc.x + w[2] * cp.x
            + w[3] * cm.y + w[4] * cc.y + w[5] * cp.y
            + w[6] * cm.z + w[7] * cc.z + w[8] * cp.z;
        out[(size_t)xx * Cn] = acc;
        cm = cc; cc = cp;
    }
}

// ---------------- launch ----------------
extern "C" void kernel_launch(void* const* d_in, const int* in_sizes, int n_in,
                              void* d_out, int out_size)
{
    const float* x     = (const float*)d_in[0];
    const float* qkv_w = (const float*)d_in[1];
    const float* dwx_w = (const float*)d_in[2];
    const float* dwx_b = (const float*)d_in[3];
    const float* dw_w  = (const float*)d_in[4];
    const float* dw_b  = (const float*)d_in[5];
    const float* pw_w  = (const float*)d_in[6];
    const float* pw_b  = (const float*)d_in[7];
    float* out = (float*)d_out;

    cudaFuncSetAttribute(gemm_mma, cudaFuncAttributeMaxDynamicSharedMemorySize,
                         GEMM_SMEM);

    // weight conversions (tiny)
    convw_kernel<<<(C3n * Cn + 255) / 256, 256>>>(qkv_w, C3n * Cn, 0);
    convw_kernel<<<(Cn * Cn + 255) / 256, 256>>>(pw_w, Cn * Cn, 1);

    // 1) coarse pooling
    pool_kernel<<<Bn * NCn, Cn>>>(x);

    // 2) coarse QKV: (2048 x 1152 x 384)
    gemm_mma<<<dim3(C3n / 128, (Bn * NCn) / 128), 512, GEMM_SMEM>>>(
        nullptr, nullptr, nullptr, C3n, 0);

    // 3) coarse routing attention + top-k
    coarse_attn_kernel<<<Bn * NHd * NCn, 256>>>();

    // 4) fine QKV: (32768 x 1152 x 384)
    gemm_mma<<<dim3(C3n / 128, (Bn * HWn) / 128), 512, GEMM_SMEM>>>(
        x, nullptr, nullptr, C3n, 1);

    // 5) fine windowed attention
    fine_attn_kernel<<<Bn * NHd * NCn, 128>>>();

    // 6) upsample+dwconv(dwx)+mix
    dwmix_kernel<<<Bn * Hn, Cn>>>(dwx_w, dwx_b);

    // 7) dwconv(dw)
    dwconv2_kernel<<<Bn * Hn, Cn>>>(dw_w, dw_b);

    // 8) pointwise projection (+bias): (32768 x 384 x 384)
    gemm_mma<<<dim3(Cn / 128, (Bn * HWn) / 128), 512, GEMM_SMEM>>>(
        nullptr, pw_b, out, Cn, 2);
}

// round 5
// speedup vs baseline: 2.7192x; 1.7762x over previous
#include <cuda_runtime.h>
#include <cuda_bf16.h>
#include <float.h>
#include <stdint.h>

// Problem constants
#define Bn   8
#define Hn   64
#define Wn   64
#define Cn   384
#define NHd  8
#define Dh   48
#define NCn  256
#define HWn  4096
#define C3n  1152
#define SCALE 0.14433756729740643f

// ---------------- scratch (device globals; no allocation) ----------------
__device__ float g_xc  [Bn * NCn * Cn];
__device__ float g_qkvc[Bn * NCn * C3n];
__device__ int   g_topk[Bn * NHd * NCn * 4];
__device__ float g_xo  [Bn * NCn * Cn];
__device__ float g_qkvf[(size_t)Bn * HWn * C3n];
__device__ float g_yo  [(size_t)Bn * HWn * Cn];
__device__ float g_z   [(size_t)Bn * HWn * Cn];
__device__ float g_z2  [(size_t)Bn * HWn * Cn];
__device__ __nv_bfloat16 g_wqh[C3n * Cn];   // qkv W hi
__device__ __nv_bfloat16 g_wql[C3n * Cn];   // qkv W lo
__device__ __nv_bfloat16 g_wph[Cn * Cn];    // pw  W hi
__device__ __nv_bfloat16 g_wpl[Cn * Cn];    // pw  W lo

// ---------------- helpers ----------------
__device__ __forceinline__ uint32_t smem_u32(const void* p) {
    uint32_t a;
    asm("{ .reg .u64 t; cvta.to.shared.u64 t, %1; cvt.u32.u64 %0, t; }"
        : "=r"(a) : "l"(p));
    return a;
}
__device__ __forceinline__ void ldmx4(uint32_t* r, uint32_t addr) {
    asm volatile("ldmatrix.sync.aligned.m8n8.x4.shared.b16 {%0,%1,%2,%3}, [%4];"
        : "=r"(r[0]), "=r"(r[1]), "=r"(r[2]), "=r"(r[3]) : "r"(addr));
}
__device__ __forceinline__ void mma16816(float* d, const uint32_t* a, const uint32_t* b) {
    asm volatile(
        "mma.sync.aligned.m16n8k16.row.col.f32.bf16.bf16.f32 "
        "{%0,%1,%2,%3}, {%4,%5,%6,%7}, {%8,%9}, {%0,%1,%2,%3};"
        : "+f"(d[0]), "+f"(d[1]), "+f"(d[2]), "+f"(d[3])
        : "r"(a[0]), "r"(a[1]), "r"(a[2]), "r"(a[3]), "r"(b[0]), "r"(b[1]));
}
__device__ __forceinline__ uint32_t pack_bf2(float x, float y) {
    unsigned short hx = __bfloat16_as_ushort(__float2bfloat16(x));
    unsigned short hy = __bfloat16_as_ushort(__float2bfloat16(y));
    return (uint32_t)hx | ((uint32_t)hy << 16);
}

// ---------------- K1: 4x4 average pool ----------------
__global__ __launch_bounds__(384) void pool_kernel(const float* __restrict__ x)
{
    int blk = blockIdx.x;
    int n = blk & 255, b = blk >> 8;
    int hc = n >> 4, wc = n & 15;
    int c = threadIdx.x;
    float s = 0.f;
#pragma unroll
    for (int i = 0; i < 4; i++)
#pragma unroll
        for (int j = 0; j < 4; j++)
            s += x[(((size_t)(b * Hn + hc * 4 + i)) * Wn + wc * 4 + j) * Cn + c];
    g_xc[((size_t)(b * NCn + n)) * Cn + c] = s * 0.0625f;
}

// ---------------- weight split-bf16 conversion ----------------
__global__ __launch_bounds__(256) void convw_kernel(
    const float* __restrict__ w, int total, int mode)
{
    int i = blockIdx.x * 256 + threadIdx.x;
    if (i >= total) return;
    float v = w[i];
    __nv_bfloat16 h = __float2bfloat16(v);
    __nv_bfloat16 l = __float2bfloat16(v - __bfloat162float(h));
    if (mode == 0) { g_wqh[i] = h; g_wql[i] = l; }
    else           { g_wph[i] = h; g_wpl[i] = l; }
}

// ---------------- tensor-core GEMM: O[M,N] = A[M,384] * W[N,384]^T --------
// split-bf16: acc = Ah*Wh + Al*Wh + Ah*Wl.  A converted in-kernel.
// 64x128 block tile, 256 threads (2x4 warps, 32x32 warp tile), BK=16,
// double-buffered smem; 2 CTAs/SM.
#define PITCH 24
#define PL_A 1536                  // 64*24 elems
#define PL_B 3072                  // 128*24 elems
#define BUFEL (2 * PL_A + 2 * PL_B)  // 9216 elems
// byte offsets within buffer
#define AHOFF 0
#define ALOFF (PL_A * 2)
#define BHOFF (PL_A * 4)
#define BLOFF (PL_A * 4 + PL_B * 2)
#define BUFBYTES (BUFEL * 2)

__global__ __launch_bounds__(256) void gemm_mma(
    const float* __restrict__ Aext, const float* __restrict__ bias,
    float* __restrict__ Oext, int N, int mode)
{
    __shared__ __nv_bfloat16 sm[2 * BUFEL];

    const float* A = (mode == 0) ? g_xc : (mode == 2) ? g_z2 : Aext;
    float*       O = (mode == 0) ? g_qkvc : (mode == 1) ? g_qkvf : Oext;
    const __nv_bfloat16* Wh = (mode == 2) ? g_wph : g_wqh;
    const __nv_bfloat16* Wl = (mode == 2) ? g_wpl : g_wql;

    int tid = threadIdx.x;
    int m0 = blockIdx.y * 64, n0 = blockIdx.x * 128;

    // A staging: thread -> (row 0..63, 4 consecutive k)
    int srowA = tid >> 2;
    int scolA = (tid & 3) * 4;
    // B staging: thread -> (row 0..127, 8 consecutive k)
    int srowB = tid >> 1;
    int scolB = (tid & 1) * 8;

    const float* aptr = A + (size_t)(m0 + srowA) * 384 + scolA;
    const __nv_bfloat16* whp = Wh + (size_t)(n0 + srowB) * 384 + scolB;
    const __nv_bfloat16* wlp = Wl + (size_t)(n0 + srowB) * 384 + scolB;

    int lane = tid & 31;
    int wid = tid >> 5;
    int mbase = (wid & 1) * 32;
    int nbase = (wid >> 1) * 32;

    uint32_t sbase = smem_u32(sm);

    int ar = lane & 15, ak = (lane >> 4) * 8;
    uint32_t offA0 = ((mbase + ar) * PITCH + ak) * 2;
    uint32_t offA1 = offA0 + 16 * PITCH * 2;
    int br = (lane & 7) + ((lane >> 4) << 3), bk = ((lane >> 3) & 1) * 8;
    uint32_t offB0 = ((nbase + br) * PITCH + bk) * 2;
    uint32_t offB1 = offB0 + 16 * PITCH * 2;

    int sidxA = srowA * PITCH + scolA;
    int sidxB = srowB * PITCH + scolB;

    float acc[2][4][4];
#pragma unroll
    for (int i = 0; i < 2; i++)
#pragma unroll
        for (int j = 0; j < 4; j++)
#pragma unroll
            for (int k = 0; k < 4; k++) acc[i][j][k] = 0.f;

    // prologue: stage chunk 0 into buffer 0
    {
        float4 a4 = *(const float4*)aptr;
        uint4  wh = *(const uint4*)whp;
        uint4  wl = *(const uint4*)wlp;
        uint32_t h01 = pack_bf2(a4.x, a4.y);
        uint32_t h23 = pack_bf2(a4.z, a4.w);
        float hx = __bfloat162float(__float2bfloat16(a4.x));
        float hy = __bfloat162float(__float2bfloat16(a4.y));
        float hz = __bfloat162float(__float2bfloat16(a4.z));
        float hw = __bfloat162float(__float2bfloat16(a4.w));
        uint32_t l01 = pack_bf2(a4.x - hx, a4.y - hy);
        uint32_t l23 = pack_bf2(a4.z - hz, a4.w - hw);
        *(uint2*)(sm + 0 * BUFEL + 0 * PL_A + sidxA) = make_uint2(h01, h23);
        *(uint2*)(sm + 0 * BUFEL + 1 * PL_A + sidxA) = make_uint2(l01, l23);
        *(uint4*)(sm + 0 * BUFEL + 2 * PL_A + sidxB) = wh;
        *(uint4*)(sm + 0 * BUFEL + 2 * PL_A + PL_B + sidxB) = wl;
    }
    __syncthreads();

    for (int kc = 0; kc < 24; kc++) {
        int cur = kc & 1;
        float4 a4n; uint4 whn, wln;
        if (kc < 23) {
            a4n = *(const float4*)(aptr + (kc + 1) * 16);
            whn = *(const uint4*)(whp + (kc + 1) * 16);
            wln = *(const uint4*)(wlp + (kc + 1) * 16);
        }

        uint32_t bb = sbase + (uint32_t)cur * BUFBYTES;
        uint32_t ah[2][4], al[2][4], bh[2][4], bl[2][4];
        ldmx4(ah[0], bb + AHOFF + offA0); ldmx4(ah[1], bb + AHOFF + offA1);
        ldmx4(al[0], bb + ALOFF + offA0); ldmx4(al[1], bb + ALOFF + offA1);
        ldmx4(bh[0], bb + BHOFF + offB0); ldmx4(bh[1], bb + BHOFF + offB1);
        ldmx4(bl[0], bb + BLOFF + offB0); ldmx4(bl[1], bb + BLOFF + offB1);
#pragma unroll
        for (int mi = 0; mi < 2; mi++)
#pragma unroll
            for (int nj = 0; nj < 2; nj++)
#pragma unroll
                for (int sub = 0; sub < 2; sub++) {
                    float* d = acc[mi][nj * 2 + sub];
                    mma16816(d, ah[mi], &bh[nj][sub * 2]);
                    mma16816(d, al[mi], &bh[nj][sub * 2]);
                    mma16816(d, ah[mi], &bl[nj][sub * 2]);
                }

        if (kc < 23) {
            int nb = cur ^ 1;
            uint32_t h01 = pack_bf2(a4n.x, a4n.y);
            uint32_t h23 = pack_bf2(a4n.z, a4n.w);
            float hx = __bfloat162float(__float2bfloat16(a4n.x));
            float hy = __bfloat162float(__float2bfloat16(a4n.y));
            float hz = __bfloat162float(__float2bfloat16(a4n.z));
            float hw = __bfloat162float(__float2bfloat16(a4n.w));
            uint32_t l01 = pack_bf2(a4n.x - hx, a4n.y - hy);
            uint32_t l23 = pack_bf2(a4n.z - hz, a4n.w - hw);
            *(uint2*)(sm + nb * BUFEL + 0 * PL_A + sidxA) = make_uint2(h01, h23);
            *(uint2*)(sm + nb * BUFEL + 1 * PL_A + sidxA) = make_uint2(l01, l23);
            *(uint4*)(sm + nb * BUFEL + 2 * PL_A + sidxB) = whn;
            *(uint4*)(sm + nb * BUFEL + 2 * PL_A + PL_B + sidxB) = wln;
        }
        __syncthreads();
    }

    // epilogue
    int rbase = m0 + mbase, cbase = n0 + nbase;
#pragma unroll
    for (int mi = 0; mi < 2; mi++)
#pragma unroll
        for (int ni = 0; ni < 4; ni++) {
            int row = rbase + mi * 16 + (lane >> 2);
            int col = cbase + ni * 8 + (lane & 3) * 2;
            float b0 = 0.f, b1 = 0.f;
            if (mode == 2) { b0 = bias[col]; b1 = bias[col + 1]; }
            float2 v0 = make_float2(acc[mi][ni][0] + b0, acc[mi][ni][1] + b1);
            float2 v1 = make_float2(acc[mi][ni][2] + b0, acc[mi][ni][3] + b1);
            *(float2*)&O[(size_t)row * N + col] = v0;
            *(float2*)&O[(size_t)(row + 8) * N + col] = v1;
        }
}

// ---------------- K3: coarse routing attention + top-k (flash-style) ------
// grid: Bn*NHd*2 = 128 blocks; 128 threads; each thread owns one query.
#define CA_SMEM (2 * 256 * 48 * 4)
__global__ __launch_bounds__(128) void coarse_attn_kernel()
{
    extern __shared__ float cas[];
    float* Ks = cas;            // [256][48]
    float* Vs = cas + 256 * 48; // [256][48]

    int bid = blockIdx.x;
    int half = bid & 1;
    int hd = (bid >> 1) & 7;
    int b = bid >> 4;
    int tid = threadIdx.x;

    const float* base = g_qkvc + (size_t)b * NCn * C3n;

    // stage K and V (256 rows x 48): 3072 float4 per plane
    for (int idx = tid; idx < 3072; idx += 128) {
        int j = idx / 12, d4 = (idx % 12) * 4;
        const float* rp = base + (size_t)j * C3n + Cn + hd * Dh + d4;
        *(float4*)&Ks[j * 48 + d4] = *(const float4*)rp;
        *(float4*)&Vs[j * 48 + d4] = *(const float4*)(rp + Cn);
    }

    // q into registers
    int q = half * 128 + tid;
    float qv[48];
    const float* qp = base + (size_t)q * C3n + hd * Dh;
#pragma unroll
    for (int i = 0; i < 12; i++) {
        float4 v = *(const float4*)(qp + i * 4);
        qv[i * 4 + 0] = v.x; qv[i * 4 + 1] = v.y;
        qv[i * 4 + 2] = v.z; qv[i * 4 + 3] = v.w;
    }
    __syncthreads();

    // pass 1: dots -> max + top4 (unscaled; scale is monotonic)
    float v0 = -FLT_MAX, v1 = -FLT_MAX, v2 = -FLT_MAX, v3 = -FLT_MAX;
    int i0 = 0, i1 = 0, i2 = 0, i3 = 0;
    for (int j = 0; j < 256; j++) {
        float a0 = 0.f, a1 = 0.f, a2 = 0.f, a3 = 0.f;
        const float* kp = &Ks[j * 48];
#pragma unroll
        for (int d4 = 0; d4 < 12; d4++) {
            float4 kv = *(const float4*)(kp + d4 * 4);
            a0 += qv[d4 * 4 + 0] * kv.x;
            a1 += qv[d4 * 4 + 1] * kv.y;
            a2 += qv[d4 * 4 + 2] * kv.z;
            a3 += qv[d4 * 4 + 3] * kv.w;
        }
        float s = (a0 + a1) + (a2 + a3);
        if (s > v3) {
            if (s > v0)      { v3 = v2; i3 = i2; v2 = v1; i2 = i1; v1 = v0; i1 = i0; v0 = s; i0 = j; }
            else if (s > v1) { v3 = v2; i3 = i2; v2 = v1; i2 = i1; v1 = s; i1 = j; }
            else if (s > v2) { v3 = v2; i3 = i2; v2 = s; i2 = j; }
            else             { v3 = s; i3 = j; }
        }
    }
    int obase = ((b * 8 + hd) * 256 + q) * 4;
    g_topk[obase + 0] = i0; g_topk[obase + 1] = i1;
    g_topk[obase + 2] = i2; g_topk[obase + 3] = i3;

    float mx = v0 * SCALE;

    // pass 2: exp + V accumulation
    float oacc[48];
#pragma unroll
    for (int d = 0; d < 48; d++) oacc[d] = 0.f;
    float psum = 0.f;
    for (int j = 0; j < 256; j++) {
        float a0 = 0.f, a1 = 0.f, a2 = 0.f, a3 = 0.f;
        const float* kp = &Ks[j * 48];
#pragma unroll
        for (int d4 = 0; d4 < 12; d4++) {
            float4 kv = *(const float4*)(kp + d4 * 4);
            a0 += qv[d4 * 4 + 0] * kv.x;
            a1 += qv[d4 * 4 + 1] * kv.y;
            a2 += qv[d4 * 4 + 2] * kv.z;
            a3 += qv[d4 * 4 + 3] * kv.w;
        }
        float p = __expf(((a0 + a1) + (a2 + a3)) * SCALE - mx);
        psum += p;
        const float* vp = &Vs[j * 48];
#pragma unroll
        for (int d4 = 0; d4 < 12; d4++) {
            float4 vv = *(const float4*)(vp + d4 * 4);
            oacc[d4 * 4 + 0] += p * vv.x;
            oacc[d4 * 4 + 1] += p * vv.y;
            oacc[d4 * 4 + 2] += p * vv.z;
            oacc[d4 * 4 + 3] += p * vv.w;
        }
    }
    float inv = 1.f / psum;
    float* op = &g_xo[((size_t)(b * NCn + q)) * Cn + hd * Dh];
#pragma unroll
    for (int i = 0; i < 12; i++) {
        float4 v = make_float4(oacc[i * 4] * inv, oacc[i * 4 + 1] * inv,
                               oacc[i * 4 + 2] * inv, oacc[i * 4 + 3] * inv);
        *(float4*)(op + i * 4) = v;
    }
}

// ---------------- K5: fine windowed attention (register-tiled) ------------
#define QT_P 18
#define KT_P 68
#define VS_P 52
#define A2_P 68
__global__ __launch_bounds__(128) void fine_attn_kernel()
{
    int bid = blockIdx.x;
    int n  = bid & 255;
    int hd = (bid >> 8) & 7;
    int b  = bid >> 11;

    __shared__ float Qt[48 * QT_P];   // Qt[dd][p], p<16
    __shared__ float Kt[48 * KT_P];   // Kt[dd][kk], kk<64
    __shared__ float Vs[64 * VS_P];   // Vs[kk][dd]
    __shared__ float A2[16 * A2_P];   // A2[p][kk]
    __shared__ int   wins[4];

    int tid = threadIdx.x;
    int hc = n >> 4, wc = n & 15;
    const float* base = g_qkvf + (size_t)b * HWn * C3n;

    if (tid < 4) wins[tid] = g_topk[(size_t)bid * 4 + tid];

    // stage Q (transposed): 16 rows x 12 float4
    for (int idx = tid; idx < 16 * 12; idx += 128) {
        int p = idx / 12, d4 = (idx % 12) * 4;
        int s = (hc * 4 + (p >> 2)) * Wn + wc * 4 + (p & 3);
        float4 v = *(const float4*)&base[(size_t)s * C3n + hd * Dh + d4];
        Qt[(d4 + 0) * QT_P + p] = v.x;
        Qt[(d4 + 1) * QT_P + p] = v.y;
        Qt[(d4 + 2) * QT_P + p] = v.z;
        Qt[(d4 + 3) * QT_P + p] = v.w;
    }
    __syncthreads();  // wins visible

    // stage K (transposed) and V: 64 rows x 12 float4 each
    for (int idx = tid; idx < 64 * 12; idx += 128) {
        int p = idx / 12, d4 = (idx % 12) * 4;
        int t = p >> 4, pl = p & 15;
        int m = wins[t];
        int s = ((m >> 4) * 4 + (pl >> 2)) * Wn + (m & 15) * 4 + (pl & 3);
        const float* row = &base[(size_t)s * C3n + hd * Dh + d4];
        float4 kv = *(const float4*)(row + Cn);
        float4 vv = *(const float4*)(row + 2 * Cn);
        Kt[(d4 + 0) * KT_P + p] = kv.x;
        Kt[(d4 + 1) * KT_P + p] = kv.y;
        Kt[(d4 + 2) * KT_P + p] = kv.z;
        Kt[(d4 + 3) * KT_P + p] = kv.w;
        *(float4*)&Vs[p * VS_P + d4] = vv;
    }
    __syncthreads();

    // QK^T: 16x64 outputs; thread (tr=tid>>4, tc=tid&15) computes 2x4
    {
        int tr = tid >> 4, tc = tid & 15;
        int r0 = tr * 2, c0 = tc * 4;
        float a0[4] = {0.f, 0.f, 0.f, 0.f};
        float a1[4] = {0.f, 0.f, 0.f, 0.f};
#pragma unroll 8
        for (int dd = 0; dd < Dh; dd++) {
            float2 qv = *(const float2*)&Qt[dd * QT_P + r0];
            float4 kv = *(const float4*)&Kt[dd * KT_P + c0];
            a0[0] += qv.x * kv.x; a0[1] += qv.x * kv.y;
            a0[2] += qv.x * kv.z; a0[3] += qv.x * kv.w;
            a1[0] += qv.y * kv.x; a1[1] += qv.y * kv.y;
            a1[2] += qv.y * kv.z; a1[3] += qv.y * kv.w;
        }
        float4 w0 = make_float4(a0[0] * SCALE, a0[1] * SCALE, a0[2] * SCALE, a0[3] * SCALE);
        float4 w1 = make_float4(a1[0] * SCALE, a1[1] * SCALE, a1[2] * SCALE, a1[3] * SCALE);
        *(float4*)&A2[r0 * A2_P + c0] = w0;
        *(float4*)&A2[(r0 + 1) * A2_P + c0] = w1;
    }
    __syncthreads();

    // softmax: 8 threads per row, 8 cols each
    {
        int row = tid >> 3, j = tid & 7;
        float* ap = &A2[row * A2_P + j * 8];
        float v[8];
        float mx = -FLT_MAX;
#pragma unroll
        for (int i = 0; i < 8; i++) { v[i] = ap[i]; mx = fmaxf(mx, v[i]); }
#pragma unroll
        for (int m = 1; m < 8; m <<= 1)
            mx = fmaxf(mx, __shfl_xor_sync(0xffffffffu, mx, m));
        float sum = 0.f;
#pragma unroll
        for (int i = 0; i < 8; i++) { v[i] = __expf(v[i] - mx); sum += v[i]; }
#pragma unroll
        for (int m = 1; m < 8; m <<= 1)
            sum += __shfl_xor_sync(0xffffffffu, sum, m);
        float inv = 1.f / sum;
#pragma unroll
        for (int i = 0; i < 8; i++) ap[i] = v[i] * inv;
    }
    __syncthreads();

    // AV: 16x48 outputs; thread (tr2=tid>>4, tc2=tid&15) computes 2x3
    {
        int tr2 = tid >> 4, tc2 = tid & 15;
        int p0 = tr2 * 2, dd0 = tc2 * 3;
        float o0[3] = {0.f, 0.f, 0.f};
        float o1[3] = {0.f, 0.f, 0.f};
#pragma unroll 8
        for (int kk = 0; kk < 64; kk++) {
            float av0 = A2[p0 * A2_P + kk];
            float av1 = A2[(p0 + 1) * A2_P + kk];
            const float* vp = &Vs[kk * VS_P + dd0];
            float v0 = vp[0], v1 = vp[1], v2 = vp[2];
            o0[0] += av0 * v0; o0[1] += av0 * v1; o0[2] += av0 * v2;
            o1[0] += av1 * v0; o1[1] += av1 * v1; o1[2] += av1 * v2;
        }
#pragma unroll
        for (int pi = 0; pi < 2; pi++) {
            int p = p0 + pi;
            int yy = hc * 4 + (p >> 2), xx = wc * 4 + (p & 3);
            float* op = &g_yo[(((size_t)(b * Hn + yy)) * Wn + xx) * Cn + hd * Dh + dd0];
            if (pi == 0) { op[0] = o0[0]; op[1] = o0[1]; op[2] = o0[2]; }
            else         { op[0] = o1[0]; op[1] = o1[1]; op[2] = o1[2]; }
        }
    }
}

// ---------------- K6: upsample(xo) -> dwconv3x3(dwx) -> mix with yo -------
__global__ __launch_bounds__(384) void dwmix_kernel(
    const float* __restrict__ dwxw, const float* __restrict__ dwxb)
{
    __shared__ float wsh[Cn * 9];
    int tid = threadIdx.x;
    for (int i = tid; i < Cn * 9; i += 384) wsh[i] = dwxw[i];
    __syncthreads();

    int b  = blockIdx.x >> 6;
    int yy = blockIdx.x & 63;
    int c  = tid;
    float w[9];
#pragma unroll
    for (int i = 0; i < 9; i++) w[i] = wsh[c * 9 + i];
    float bias = dwxb[c];

    const float* xob = g_xo + (size_t)b * NCn * Cn + c;
    bool up = yy > 0, dn = yy < 63;
    int ru = (yy - 1) >> 2, rm = yy >> 2, rd = (yy + 1) >> 2;

    float3 cm = make_float3(0.f, 0.f, 0.f), cc, cp;
    cc.x = up ? xob[(size_t)(ru * 16) * Cn] : 0.f;
    cc.y = xob[(size_t)(rm * 16) * Cn];
    cc.z = dn ? xob[(size_t)(rd * 16) * Cn] : 0.f;

    size_t pix0 = ((size_t)(b * Hn + yy)) * Wn;
    for (int xx = 0; xx < 64; xx++) {
        if (xx < 63) {
            int xc4 = (xx + 1) >> 2;
            cp.x = up ? xob[(size_t)(ru * 16 + xc4) * Cn] : 0.f;
            cp.y = xob[(size_t)(rm * 16 + xc4) * Cn];
            cp.z = dn ? xob[(size_t)(rd * 16 + xc4) * Cn] : 0.f;
        } else {
            cp = make_float3(0.f, 0.f, 0.f);
        }
        float acc = bias
            + w[0] * cm.x + w[1] * cc.x + w[2] * cp.x
            + w[3] * cm.y + w[4] * cc.y + w[5] * cp.y
            + w[6] * cm.z + w[7] * cc.z + w[8] * cp.z;
        size_t pix = pix0 + xx;
        g_z[pix * Cn + c] = 0.5f * acc + 0.5f * g_yo[pix * Cn + c];
        cm = cc; cc = cp;
    }
}

// ---------------- K7: dwconv3x3(dw) on z -> z2 ----------------
__global__ __launch_bounds__(384) void dwconv2_kernel(
    const float* __restrict__ dww, const float* __restrict__ dwb)
{
    __shared__ float wsh[Cn * 9];
    int tid = threadIdx.x;
    for (int i = tid; i < Cn * 9; i += 384) wsh[i] = dww[i];
    __syncthreads();

    int b  = blockIdx.x >> 6;
    int yy = blockIdx.x & 63;
    int c  = tid;
    float w[9];
#pragma unroll
    for (int i = 0; i < 9; i++) w[i] = wsh[c * 9 + i];
    float bias = dwb[c];

    const float* zb = g_z + (size_t)b * HWn * Cn + c;
    bool up = yy > 0, dn = yy < 63;
    size_t rowm = (size_t)yy * Wn;

    float3 cm = make_float3(0.f, 0.f, 0.f), cc, cp;
    cc.x = up ? zb[(rowm - Wn) * Cn] : 0.f;
    cc.y = zb[rowm * Cn];
    cc.z = dn ? zb[(rowm + Wn) * Cn] : 0.f;

    float* out = g_z2 + ((size_t)b * HWn + rowm) * Cn + c;
    for (int xx = 0; xx < 64; xx++) {
        if (xx < 63) {
            size_t bcol = rowm + xx + 1;
            cp.x = up ? zb[(bcol - Wn) * Cn] : 0.f;
            cp.y = zb[bcol * Cn];
            cp.z = dn ? zb[(bcol + Wn) * Cn] : 0.f;
        } else {
            cp = make_float3(0.f, 0.f, 0.f);
        }
        float acc = bias
            + w[0] * cm.x + w[1] * cc.x + w[2] * cp.x
            + w[3] * cm.y + w[4] * cc.y + w[5] * cp.y
            + w[6] * cm.z + w[7] * cc.z + w[8] * cp.z;
        out[(size_t)xx * Cn] = acc;
        cm = cc; cc = cp;
    }
}

// ---------------- launch ----------------
extern "C" void kernel_launch(void* const* d_in, const int* in_sizes, int n_in,
                              void* d_out, int out_size)
{
    const float* x     = (const float*)d_in[0];
    const float* qkv_w = (const float*)d_in[1];
    const float* dwx_w = (const float*)d_in[2];
    const float* dwx_b = (const float*)d_in[3];
    const float* dw_w  = (const float*)d_in[4];
    const float* dw_b  = (const float*)d_in[5];
    const float* pw_w  = (const float*)d_in[6];
    const float* pw_b  = (const float*)d_in[7];
    float* out = (float*)d_out;

    cudaFuncSetAttribute(coarse_attn_kernel,
                         cudaFuncAttributeMaxDynamicSharedMemorySize, CA_SMEM);

    // weight conversions (tiny)
    convw_kernel<<<(C3n * Cn + 255) / 256, 256>>>(qkv_w, C3n * Cn, 0);
    convw_kernel<<<(Cn * Cn + 255) / 256, 256>>>(pw_w, Cn * Cn, 1);

    // 1) coarse pooling
    pool_kernel<<<Bn * NCn, Cn>>>(x);

    // 2) coarse QKV: (2048 x 1152 x 384)
    gemm_mma<<<dim3(C3n / 128, (Bn * NCn) / 64), 256>>>(
        nullptr, nullptr, nullptr, C3n, 0);

    // 3) coarse routing attention + top-k
    coarse_attn_kernel<<<Bn * NHd * 2, 128, CA_SMEM>>>();

    // 4) fine QKV: (32768 x 1152 x 384)
    gemm_mma<<<dim3(C3n / 128, (Bn * HWn) / 64), 256>>>(
        x, nullptr, nullptr, C3n, 1);

    // 5) fine windowed attention
    fine_attn_kernel<<<Bn * NHd * NCn, 128>>>();

    // 6) upsample+dwconv(dwx)+mix
    dwmix_kernel<<<Bn * Hn, Cn>>>(dwx_w, dwx_b);

    // 7) dwconv(dw)
    dwconv2_kernel<<<Bn * Hn, Cn>>>(dw_w, dw_b);

    // 8) pointwise projection (+bias): (32768 x 384 x 384)
    gemm_mma<<<dim3(Cn / 128, (Bn * HWn) / 64), 256>>>(
        nullptr, pw_b, out, Cn, 2);
}

// round 6
// speedup vs baseline: 3.1058x; 1.1422x over previous
#include <cuda_runtime.h>
#include <cuda_bf16.h>
#include <float.h>
#include <stdint.h>

// Problem constants
#define Bn   8
#define Hn   64
#define Wn   64
#define Cn   384
#define NHd  8
#define Dh   48
#define NCn  256
#define HWn  4096
#define C3n  1152
#define SCALE 0.14433756729740643f

// ---------------- scratch (device globals; no allocation) ----------------
__device__ float g_xc  [Bn * NCn * Cn];
__device__ float g_qkvc[Bn * NCn * C3n];
__device__ int   g_topk[Bn * NHd * NCn * 4];
__device__ float g_xo  [Bn * NCn * Cn];
__device__ float g_qkvf[(size_t)Bn * HWn * C3n];
__device__ float g_yo  [(size_t)Bn * HWn * Cn];
__device__ float g_z   [(size_t)Bn * HWn * Cn];
__device__ float g_z2  [(size_t)Bn * HWn * Cn];
#define PLOFF (32768 * 384)
__device__ __nv_bfloat16 g_abf[2 * PLOFF];  // A hi plane, lo plane
__device__ __nv_bfloat16 g_wqh[C3n * Cn];   // qkv W hi
__device__ __nv_bfloat16 g_wql[C3n * Cn];   // qkv W lo
__device__ __nv_bfloat16 g_wph[Cn * Cn];    // pw  W hi
__device__ __nv_bfloat16 g_wpl[Cn * Cn];    // pw  W lo

// ---------------- helpers ----------------
__device__ __forceinline__ uint32_t smem_u32(const void* p) {
    uint32_t a;
    asm("{ .reg .u64 t; cvta.to.shared.u64 t, %1; cvt.u32.u64 %0, t; }"
        : "=r"(a) : "l"(p));
    return a;
}
__device__ __forceinline__ void ldmx4(uint32_t* r, uint32_t addr) {
    asm volatile("ldmatrix.sync.aligned.m8n8.x4.shared.b16 {%0,%1,%2,%3}, [%4];"
        : "=r"(r[0]), "=r"(r[1]), "=r"(r[2]), "=r"(r[3]) : "r"(addr));
}
__device__ __forceinline__ void mma16816(float* d, const uint32_t* a, const uint32_t* b) {
    asm volatile(
        "mma.sync.aligned.m16n8k16.row.col.f32.bf16.bf16.f32 "
        "{%0,%1,%2,%3}, {%4,%5,%6,%7}, {%8,%9}, {%0,%1,%2,%3};"
        : "+f"(d[0]), "+f"(d[1]), "+f"(d[2]), "+f"(d[3])
        : "r"(a[0]), "r"(a[1]), "r"(a[2]), "r"(a[3]), "r"(b[0]), "r"(b[1]));
}
__device__ __forceinline__ uint32_t pack_bf2(float x, float y) {
    unsigned short hx = __bfloat16_as_ushort(__float2bfloat16(x));
    unsigned short hy = __bfloat16_as_ushort(__float2bfloat16(y));
    return (uint32_t)hx | ((uint32_t)hy << 16);
}
__device__ __forceinline__ void cpa16(uint32_t saddr, const void* g) {
    asm volatile("cp.async.cg.shared.global [%0], [%1], 16;"
                 :: "r"(saddr), "l"(g) : "memory");
}
__device__ __forceinline__ void cp_commit() {
    asm volatile("cp.async.commit_group;" ::: "memory");
}
__device__ __forceinline__ void cp_wait1() {
    asm volatile("cp.async.wait_group 1;" ::: "memory");
}

// ---------------- K1: 4x4 average pool ----------------
__global__ __launch_bounds__(384) void pool_kernel(const float* __restrict__ x)
{
    int blk = blockIdx.x;
    int n = blk & 255, b = blk >> 8;
    int hc = n >> 4, wc = n & 15;
    int c = threadIdx.x;
    float s = 0.f;
#pragma unroll
    for (int i = 0; i < 4; i++)
#pragma unroll
        for (int j = 0; j < 4; j++)
            s += x[(((size_t)(b * Hn + hc * 4 + i)) * Wn + wc * 4 + j) * Cn + c];
    g_xc[((size_t)(b * NCn + n)) * Cn + c] = s * 0.0625f;
}

// ---------------- weight split-bf16 conversion ----------------
__global__ __launch_bounds__(256) void convw_kernel(
    const float* __restrict__ w, int total, int mode)
{
    int i = blockIdx.x * 256 + threadIdx.x;
    if (i >= total) return;
    float v = w[i];
    __nv_bfloat16 h = __float2bfloat16(v);
    __nv_bfloat16 l = __float2bfloat16(v - __bfloat162float(h));
    if (mode == 0) { g_wqh[i] = h; g_wql[i] = l; }
    else           { g_wph[i] = h; g_wpl[i] = l; }
}

// ---------------- A split-bf16 conversion (float -> hi/lo planes) ---------
// mode 0: srcExt ; mode 1: g_xc ; mode 2: g_z2.  n4 = M*96 float4s.
__global__ __launch_bounds__(256) void convA_kernel(
    const float* __restrict__ srcExt, int n4, int mode)
{
    int i = blockIdx.x * 256 + threadIdx.x;
    if (i >= n4) return;
    const float* src = (mode == 1) ? g_xc : (mode == 2) ? g_z2 : srcExt;
    float4 v = ((const float4*)src)[i];
    uint32_t h01 = pack_bf2(v.x, v.y);
    uint32_t h23 = pack_bf2(v.z, v.w);
    float hx = __bfloat162float(__float2bfloat16(v.x));
    float hy = __bfloat162float(__float2bfloat16(v.y));
    float hz = __bfloat162float(__float2bfloat16(v.z));
    float hw = __bfloat162float(__float2bfloat16(v.w));
    uint32_t l01 = pack_bf2(v.x - hx, v.y - hy);
    uint32_t l23 = pack_bf2(v.z - hz, v.w - hw);
    *(uint2*)(g_abf + (size_t)i * 4)         = make_uint2(h01, h23);
    *(uint2*)(g_abf + PLOFF + (size_t)i * 4) = make_uint2(l01, l23);
}

// ---------------- tensor-core GEMM: O[M,N] = A[M,384] * W[N,384]^T --------
// All operands bf16 (A pre-split in g_abf).  acc = Ah*Wh + Al*Wh + Ah*Wl.
// 128x128 tile, 256 threads (4x2 warps, 32x64 warp tile), BK=16,
// 3-stage cp.async pipeline.
#define PITCH 24
#define AHOFF 0
#define ALOFF 6144
#define BHOFF 12288
#define BLOFF 18432
#define STAGEBYTES 24576
#define GSMEM (3 * STAGEBYTES)

__global__ __launch_bounds__(256, 2) void gemm_mma(
    const float* __restrict__ bias, float* __restrict__ Oext, int N, int mode)
{
    extern __shared__ __nv_bfloat16 sm[];

    float* O = (mode == 0) ? g_qkvc : (mode == 1) ? g_qkvf : Oext;
    const __nv_bfloat16* Wh = (mode == 2) ? g_wph : g_wqh;
    const __nv_bfloat16* Wl = (mode == 2) ? g_wpl : g_wql;

    int tid = threadIdx.x;
    int m0 = blockIdx.y * 128, n0 = blockIdx.x * 128;

    // staging: thread -> (row 0..127, k-half 0/1); 4 cp.async per stage
    int row = tid >> 1, kh = tid & 1;
    const __nv_bfloat16* aH = g_abf + (size_t)(m0 + row) * 384 + kh * 8;
    const __nv_bfloat16* aL = aH + PLOFF;
    const __nv_bfloat16* bH = Wh + (size_t)(n0 + row) * 384 + kh * 8;
    const __nv_bfloat16* bL = Wl + (size_t)(n0 + row) * 384 + kh * 8;
    uint32_t sbase = smem_u32(sm);
    uint32_t ssoff = (uint32_t)(row * PITCH + kh * 8) * 2;

    int lane = tid & 31;
    int wid = tid >> 5;
    int mbase = (wid & 3) * 32;
    int nbase = (wid >> 2) * 64;

    int ar = lane & 15, ak = (lane >> 4) * 8;
    uint32_t offA0 = ((mbase + ar) * PITCH + ak) * 2;
    int br = (lane & 7) + ((lane >> 4) << 3), bk = ((lane >> 3) & 1) * 8;
    uint32_t offB0 = ((nbase + br) * PITCH + bk) * 2;

    float acc[2][8][4];
#pragma unroll
    for (int i = 0; i < 2; i++)
#pragma unroll
        for (int j = 0; j < 8; j++)
#pragma unroll
            for (int k = 0; k < 4; k++) acc[i][j][k] = 0.f;

    // prologue: stages 0,1 <- chunks 0,1
#pragma unroll
    for (int s = 0; s < 2; s++) {
        uint32_t sb = sbase + s * STAGEBYTES + ssoff;
        cpa16(sb + AHOFF, aH + s * 16);
        cpa16(sb + ALOFF, aL + s * 16);
        cpa16(sb + BHOFF, bH + s * 16);
        cpa16(sb + BLOFF, bL + s * 16);
        cp_commit();
    }

    int sc = 0, sl = 2;
    for (int kc = 0; kc < 24; kc++) {
        cp_wait1();
        __syncthreads();

        // issue chunk kc+2 into stage sl (overlaps with mma below)
        if (kc < 22) {
            uint32_t sb = sbase + sl * STAGEBYTES + ssoff;
            const int kk = (kc + 2) * 16;
            cpa16(sb + AHOFF, aH + kk);
            cpa16(sb + ALOFF, aL + kk);
            cpa16(sb + BHOFF, bH + kk);
            cpa16(sb + BLOFF, bL + kk);
        }
        cp_commit();
        sl = (sl == 2) ? 0 : sl + 1;

        uint32_t bb = sbase + sc * STAGEBYTES;
        sc = (sc == 2) ? 0 : sc + 1;

        uint32_t ah[2][4], al[2][4], bf[4][4];
        ldmx4(ah[0], bb + AHOFF + offA0);
        ldmx4(ah[1], bb + AHOFF + offA0 + 768);
        ldmx4(al[0], bb + ALOFF + offA0);
        ldmx4(al[1], bb + ALOFF + offA0 + 768);
#pragma unroll
        for (int g = 0; g < 4; g++)
            ldmx4(bf[g], bb + BHOFF + offB0 + g * 768);
#pragma unroll
        for (int mi = 0; mi < 2; mi++)
#pragma unroll
            for (int g = 0; g < 4; g++)
#pragma unroll
                for (int sub = 0; sub < 2; sub++) {
                    float* d = acc[mi][g * 2 + sub];
                    mma16816(d, ah[mi], &bf[g][sub * 2]);
                    mma16816(d, al[mi], &bf[g][sub * 2]);
                }
#pragma unroll
        for (int g = 0; g < 4; g++)
            ldmx4(bf[g], bb + BLOFF + offB0 + g * 768);
#pragma unroll
        for (int mi = 0; mi < 2; mi++)
#pragma unroll
            for (int g = 0; g < 4; g++)
#pragma unroll
                for (int sub = 0; sub < 2; sub++)
                    mma16816(acc[mi][g * 2 + sub], ah[mi], &bf[g][sub * 2]);
    }

    // epilogue
    int rbase = m0 + mbase, cbase = n0 + nbase;
#pragma unroll
    for (int mi = 0; mi < 2; mi++)
#pragma unroll
        for (int ni = 0; ni < 8; ni++) {
            int rrow = rbase + mi * 16 + (lane >> 2);
            int col = cbase + ni * 8 + (lane & 3) * 2;
            float b0 = 0.f, b1 = 0.f;
            if (mode == 2) { b0 = bias[col]; b1 = bias[col + 1]; }
            float2 v0 = make_float2(acc[mi][ni][0] + b0, acc[mi][ni][1] + b1);
            float2 v1 = make_float2(acc[mi][ni][2] + b0, acc[mi][ni][3] + b1);
            *(float2*)&O[(size_t)rrow * N + col] = v0;
            *(float2*)&O[(size_t)(rrow + 8) * N + col] = v1;
        }
}

// ---------------- K3: coarse routing attention + top-k (flash-style) ------
#define CA_SMEM (2 * 256 * 48 * 4)
__global__ __launch_bounds__(128) void coarse_attn_kernel()
{
    extern __shared__ float cas[];
    float* Ks = cas;
    float* Vs = cas + 256 * 48;

    int bid = blockIdx.x;
    int half = bid & 1;
    int hd = (bid >> 1) & 7;
    int b = bid >> 4;
    int tid = threadIdx.x;

    const float* base = g_qkvc + (size_t)b * NCn * C3n;

    for (int idx = tid; idx < 3072; idx += 128) {
        int j = idx / 12, d4 = (idx % 12) * 4;
        const float* rp = base + (size_t)j * C3n + Cn + hd * Dh + d4;
        *(float4*)&Ks[j * 48 + d4] = *(const float4*)rp;
        *(float4*)&Vs[j * 48 + d4] = *(const float4*)(rp + Cn);
    }

    int q = half * 128 + tid;
    float qv[48];
    const float* qp = base + (size_t)q * C3n + hd * Dh;
#pragma unroll
    for (int i = 0; i < 12; i++) {
        float4 v = *(const float4*)(qp + i * 4);
        qv[i * 4 + 0] = v.x; qv[i * 4 + 1] = v.y;
        qv[i * 4 + 2] = v.z; qv[i * 4 + 3] = v.w;
    }
    __syncthreads();

    float v0 = -FLT_MAX, v1 = -FLT_MAX, v2 = -FLT_MAX, v3 = -FLT_MAX;
    int i0 = 0, i1 = 0, i2 = 0, i3 = 0;
    for (int j = 0; j < 256; j++) {
        float a0 = 0.f, a1 = 0.f, a2 = 0.f, a3 = 0.f;
        const float* kp = &Ks[j * 48];
#pragma unroll
        for (int d4 = 0; d4 < 12; d4++) {
            float4 kv = *(const float4*)(kp + d4 * 4);
            a0 += qv[d4 * 4 + 0] * kv.x;
            a1 += qv[d4 * 4 + 1] * kv.y;
            a2 += qv[d4 * 4 + 2] * kv.z;
            a3 += qv[d4 * 4 + 3] * kv.w;
        }
        float s = (a0 + a1) + (a2 + a3);
        if (s > v3) {
            if (s > v0)      { v3 = v2; i3 = i2; v2 = v1; i2 = i1; v1 = v0; i1 = i0; v0 = s; i0 = j; }
            else if (s > v1) { v3 = v2; i3 = i2; v2 = v1; i2 = i1; v1 = s; i1 = j; }
            else if (s > v2) { v3 = v2; i3 = i2; v2 = s; i2 = j; }
            else             { v3 = s; i3 = j; }
        }
    }
    int obase = ((b * 8 + hd) * 256 + q) * 4;
    g_topk[obase + 0] = i0; g_topk[obase + 1] = i1;
    g_topk[obase + 2] = i2; g_topk[obase + 3] = i3;

    float mx = v0 * SCALE;

    float oacc[48];
#pragma unroll
    for (int d = 0; d < 48; d++) oacc[d] = 0.f;
    float psum = 0.f;
    for (int j = 0; j < 256; j++) {
        float a0 = 0.f, a1 = 0.f, a2 = 0.f, a3 = 0.f;
        const float* kp = &Ks[j * 48];
#pragma unroll
        for (int d4 = 0; d4 < 12; d4++) {
            float4 kv = *(const float4*)(kp + d4 * 4);
            a0 += qv[d4 * 4 + 0] * kv.x;
            a1 += qv[d4 * 4 + 1] * kv.y;
            a2 += qv[d4 * 4 + 2] * kv.z;
            a3 += qv[d4 * 4 + 3] * kv.w;
        }
        float p = __expf(((a0 + a1) + (a2 + a3)) * SCALE - mx);
        psum += p;
        const float* vp = &Vs[j * 48];
#pragma unroll
        for (int d4 = 0; d4 < 12; d4++) {
            float4 vv = *(const float4*)(vp + d4 * 4);
            oacc[d4 * 4 + 0] += p * vv.x;
            oacc[d4 * 4 + 1] += p * vv.y;
            oacc[d4 * 4 + 2] += p * vv.z;
            oacc[d4 * 4 + 3] += p * vv.w;
        }
    }
    float inv = 1.f / psum;
    float* op = &g_xo[((size_t)(b * NCn + q)) * Cn + hd * Dh];
#pragma unroll
    for (int i = 0; i < 12; i++) {
        float4 v = make_float4(oacc[i * 4] * inv, oacc[i * 4 + 1] * inv,
                               oacc[i * 4 + 2] * inv, oacc[i * 4 + 3] * inv);
        *(float4*)(op + i * 4) = v;
    }
}

// ---------------- K5: fine windowed attention (register-tiled) ------------
#define QT_P 18
#define KT_P 68
#define VS_P 52
#define A2_P 68
__global__ __launch_bounds__(128) void fine_attn_kernel()
{
    int bid = blockIdx.x;
    int n  = bid & 255;
    int hd = (bid >> 8) & 7;
    int b  = bid >> 11;

    __shared__ float Qt[48 * QT_P];
    __shared__ float Kt[48 * KT_P];
    __shared__ float Vs[64 * VS_P];
    __shared__ float A2[16 * A2_P];
    __shared__ int   wins[4];

    int tid = threadIdx.x;
    int hc = n >> 4, wc = n & 15;
    const float* base = g_qkvf + (size_t)b * HWn * C3n;

    if (tid < 4) wins[tid] = g_topk[(size_t)bid * 4 + tid];

    for (int idx = tid; idx < 16 * 12; idx += 128) {
        int p = idx / 12, d4 = (idx % 12) * 4;
        int s = (hc * 4 + (p >> 2)) * Wn + wc * 4 + (p & 3);
        float4 v = *(const float4*)&base[(size_t)s * C3n + hd * Dh + d4];
        Qt[(d4 + 0) * QT_P + p] = v.x;
        Qt[(d4 + 1) * QT_P + p] = v.y;
        Qt[(d4 + 2) * QT_P + p] = v.z;
        Qt[(d4 + 3) * QT_P + p] = v.w;
    }
    __syncthreads();

    for (int idx = tid; idx < 64 * 12; idx += 128) {
        int p = idx / 12, d4 = (idx % 12) * 4;
        int t = p >> 4, pl = p & 15;
        int m = wins[t];
        int s = ((m >> 4) * 4 + (pl >> 2)) * Wn + (m & 15) * 4 + (pl & 3);
        const float* rw = &base[(size_t)s * C3n + hd * Dh + d4];
        float4 kv = *(const float4*)(rw + Cn);
        float4 vv = *(const float4*)(rw + 2 * Cn);
        Kt[(d4 + 0) * KT_P + p] = kv.x;
        Kt[(d4 + 1) * KT_P + p] = kv.y;
        Kt[(d4 + 2) * KT_P + p] = kv.z;
        Kt[(d4 + 3) * KT_P + p] = kv.w;
        *(float4*)&Vs[p * VS_P + d4] = vv;
    }
    __syncthreads();

    {
        int tr = tid >> 4, tc = tid & 15;
        int r0 = tr * 2, c0 = tc * 4;
        float a0[4] = {0.f, 0.f, 0.f, 0.f};
        float a1[4] = {0.f, 0.f, 0.f, 0.f};
#pragma unroll 8
        for (int dd = 0; dd < Dh; dd++) {
            float2 qv = *(const float2*)&Qt[dd * QT_P + r0];
            float4 kv = *(const float4*)&Kt[dd * KT_P + c0];
            a0[0] += qv.x * kv.x; a0[1] += qv.x * kv.y;
            a0[2] += qv.x * kv.z; a0[3] += qv.x * kv.w;
            a1[0] += qv.y * kv.x; a1[1] += qv.y * kv.y;
            a1[2] += qv.y * kv.z; a1[3] += qv.y * kv.w;
        }
        float4 w0 = make_float4(a0[0] * SCALE, a0[1] * SCALE, a0[2] * SCALE, a0[3] * SCALE);
        float4 w1 = make_float4(a1[0] * SCALE, a1[1] * SCALE, a1[2] * SCALE, a1[3] * SCALE);
        *(float4*)&A2[r0 * A2_P + c0] = w0;
        *(float4*)&A2[(r0 + 1) * A2_P + c0] = w1;
    }
    __syncthreads();

    {
        int row = tid >> 3, j = tid & 7;
        float* ap = &A2[row * A2_P + j * 8];
        float v[8];
        float mx = -FLT_MAX;
#pragma unroll
        for (int i = 0; i < 8; i++) { v[i] = ap[i]; mx = fmaxf(mx, v[i]); }
#pragma unroll
        for (int m = 1; m < 8; m <<= 1)
            mx = fmaxf(mx, __shfl_xor_sync(0xffffffffu, mx, m));
        float sum = 0.f;
#pragma unroll
        for (int i = 0; i < 8; i++) { v[i] = __expf(v[i] - mx); sum += v[i]; }
#pragma unroll
        for (int m = 1; m < 8; m <<= 1)
            sum += __shfl_xor_sync(0xffffffffu, sum, m);
        float inv = 1.f / sum;
#pragma unroll
        for (int i = 0; i < 8; i++) ap[i] = v[i] * inv;
    }
    __syncthreads();

    {
        int tr2 = tid >> 4, tc2 = tid & 15;
        int p0 = tr2 * 2, dd0 = tc2 * 3;
        float o0[3] = {0.f, 0.f, 0.f};
        float o1[3] = {0.f, 0.f, 0.f};
#pragma unroll 8
        for (int kk = 0; kk < 64; kk++) {
            float av0 = A2[p0 * A2_P + kk];
            float av1 = A2[(p0 + 1) * A2_P + kk];
            const float* vp = &Vs[kk * VS_P + dd0];
            float v0 = vp[0], v1 = vp[1], v2 = vp[2];
            o0[0] += av0 * v0; o0[1] += av0 * v1; o0[2] += av0 * v2;
            o1[0] += av1 * v0; o1[1] += av1 * v1; o1[2] += av1 * v2;
        }
#pragma unroll
        for (int pi = 0; pi < 2; pi++) {
            int p = p0 + pi;
            int yy = hc * 4 + (p >> 2), xx = wc * 4 + (p & 3);
            float* op = &g_yo[(((size_t)(b * Hn + yy)) * Wn + xx) * Cn + hd * Dh + dd0];
            if (pi == 0) { op[0] = o0[0]; op[1] = o0[1]; op[2] = o0[2]; }
            else         { op[0] = o1[0]; op[1] = o1[1]; op[2] = o1[2]; }
        }
    }
}

// ---------------- K6: upsample(xo) -> dwconv3x3(dwx) -> mix with yo -------
__global__ __launch_bounds__(384) void dwmix_kernel(
    const float* __restrict__ dwxw, const float* __restrict__ dwxb)
{
    __shared__ float wsh[Cn * 9];
    int tid = threadIdx.x;
    for (int i = tid; i < Cn * 9; i += 384) wsh[i] = dwxw[i];
    __syncthreads();

    int b  = blockIdx.x >> 6;
    int yy = blockIdx.x & 63;
    int c  = tid;
    float w[9];
#pragma unroll
    for (int i = 0; i < 9; i++) w[i] = wsh[c * 9 + i];
    float bias = dwxb[c];

    const float* xob = g_xo + (size_t)b * NCn * Cn + c;
    bool up = yy > 0, dn = yy < 63;
    int ru = (yy - 1) >> 2, rm = yy >> 2, rd = (yy + 1) >> 2;

    float3 cm = make_float3(0.f, 0.f, 0.f), cc, cp;
    cc.x = up ? xob[(size_t)(ru * 16) * Cn] : 0.f;
    cc.y = xob[(size_t)(rm * 16) * Cn];
    cc.z = dn ? xob[(size_t)(rd * 16) * Cn] : 0.f;

    size_t pix0 = ((size_t)(b * Hn + yy)) * Wn;
    for (int xx = 0; xx < 64; xx++) {
        if (xx < 63) {
            int xc4 = (xx + 1) >> 2;
            cp.x = up ? xob[(size_t)(ru * 16 + xc4) * Cn] : 0.f;
            cp.y = xob[(size_t)(rm * 16 + xc4) * Cn];
            cp.z = dn ? xob[(size_t)(rd * 16 + xc4) * Cn] : 0.f;
        } else {
            cp = make_float3(0.f, 0.f, 0.f);
        }
        float acc = bias
            + w[0] * cm.x + w[1] * cc.x + w[2] * cp.x
            + w[3] * cm.y + w[4] * cc.y + w[5] * cp.y
            + w[6] * cm.z + w[7] * cc.z + w[8] * cp.z;
        size_t pix = pix0 + xx;
        g_z[pix * Cn + c] = 0.5f * acc + 0.5f * g_yo[pix * Cn + c];
        cm = cc; cc = cp;
    }
}

// ---------------- K7: dwconv3x3(dw) on z -> z2 ----------------
__global__ __launch_bounds__(384) void dwconv2_kernel(
    const float* __restrict__ dww, const float* __restrict__ dwb)
{
    __shared__ float wsh[Cn * 9];
    int tid = threadIdx.x;
    for (int i = tid; i < Cn * 9; i += 384) wsh[i] = dww[i];
    __syncthreads();

    int b  = blockIdx.x >> 6;
    int yy = blockIdx.x & 63;
    int c  = tid;
    float w[9];
#pragma unroll
    for (int i = 0; i < 9; i++) w[i] = wsh[c * 9 + i];
    float bias = dwb[c];

    const float* zb = g_z + (size_t)b * HWn * Cn + c;
    bool up = yy > 0, dn = yy < 63;
    size_t rowm = (size_t)yy * Wn;

    float3 cm = make_float3(0.f, 0.f, 0.f), cc, cp;
    cc.x = up ? zb[(rowm - Wn) * Cn] : 0.f;
    cc.y = zb[rowm * Cn];
    cc.z = dn ? zb[(rowm + Wn) * Cn] : 0.f;

    float* out = g_z2 + ((size_t)b * HWn + rowm) * Cn + c;
    for (int xx = 0; xx < 64; xx++) {
        if (xx < 63) {
            size_t bcol = rowm + xx + 1;
            cp.x = up ? zb[(bcol - Wn) * Cn] : 0.f;
            cp.y = zb[bcol * Cn];
            cp.z = dn ? zb[(bcol + Wn) * Cn] : 0.f;
        } else {
            cp = make_float3(0.f, 0.f, 0.f);
        }
        float acc = bias
            + w[0] * cm.x + w[1] * cc.x + w[2] * cp.x
            + w[3] * cm.y + w[4] * cc.y + w[5] * cp.y
            + w[6] * cm.z + w[7] * cc.z + w[8] * cp.z;
        out[(size_t)xx * Cn] = acc;
        cm = cc; cc = cp;
    }
}

// ---------------- launch ----------------
extern "C" void kernel_launch(void* const* d_in, const int* in_sizes, int n_in,
                              void* d_out, int out_size)
{
    const float* x     = (const float*)d_in[0];
    const float* qkv_w = (const float*)d_in[1];
    const float* dwx_w = (const float*)d_in[2];
    const float* dwx_b = (const float*)d_in[3];
    const float* dw_w  = (const float*)d_in[4];
    const float* dw_b  = (const float*)d_in[5];
    const float* pw_w  = (const float*)d_in[6];
    const float* pw_b  = (const float*)d_in[7];
    float* out = (float*)d_out;

    cudaFuncSetAttribute(gemm_mma, cudaFuncAttributeMaxDynamicSharedMemorySize,
                         GSMEM);
    cudaFuncSetAttribute(coarse_attn_kernel,
                         cudaFuncAttributeMaxDynamicSharedMemorySize, CA_SMEM);

    // weight conversions (tiny)
    convw_kernel<<<(C3n * Cn + 255) / 256, 256>>>(qkv_w, C3n * Cn, 0);
    convw_kernel<<<(Cn * Cn + 255) / 256, 256>>>(pw_w, Cn * Cn, 1);

    // 1) coarse pooling + A conversion
    pool_kernel<<<Bn * NCn, Cn>>>(x);
    convA_kernel<<<(Bn * NCn * 96 + 255) / 256, 256>>>(nullptr, Bn * NCn * 96, 1);

    // 2) coarse QKV: (2048 x 1152 x 384)
    gemm_mma<<<dim3(C3n / 128, (Bn * NCn) / 128), 256, GSMEM>>>(
        nullptr, nullptr, C3n, 0);

    // 3) coarse routing attention + top-k
    coarse_attn_kernel<<<Bn * NHd * 2, 128, CA_SMEM>>>();

    // 4) fine QKV: (32768 x 1152 x 384)
    convA_kernel<<<(Bn * HWn * 96 + 255) / 256, 256>>>(x, Bn * HWn * 96, 0);
    gemm_mma<<<dim3(C3n / 128, (Bn * HWn) / 128), 256, GSMEM>>>(
        nullptr, nullptr, C3n, 1);

    // 5) fine windowed attention
    fine_attn_kernel<<<Bn * NHd * NCn, 128>>>();

    // 6) upsample+dwconv(dwx)+mix
    dwmix_kernel<<<Bn * Hn, Cn>>>(dwx_w, dwx_b);

    // 7) dwconv(dw)
    dwconv2_kernel<<<Bn * Hn, Cn>>>(dw_w, dw_b);

    // 8) pointwise projection (+bias): (32768 x 384 x 384)
    convA_kernel<<<(Bn * HWn * 96 + 255) / 256, 256>>>(nullptr, Bn * HWn * 96, 2);
    gemm_mma<<<dim3(Cn / 128, (Bn * HWn) / 128), 256, GSMEM>>>(
        pw_b, out, Cn, 2);
}